// round 11
// baseline (speedup 1.0000x reference)
#include <cuda_runtime.h>
#include <math.h>

#define NANCH 9216
#define NPAD1 16384
#define NBW1  144
#define KP    2000
#define NPAD2 2048
#define NBW2  32
#define FK    6272
#define FULLM 0xffffffffu

// output offsets (floats)
#define O_RPNL  0
#define O_RPND  18432
#define O_PROPS 55296
#define O_ANCH  63296
#define O_RCL   100160
#define O_RCD   104160
#define O_DETS  112160
#define O_SC    120160

// ---------------- device scratch ----------------
__device__ __align__(16) float g_featT[32*32*128];
__device__ __align__(16) float g_hT[32*32*128];
__device__ __align__(16) float g_bbT[768*128];
__device__ __align__(16) float g_rwT[1152*128];
__device__ __align__(16) float g_fc1wP[1024*FK];
__device__ __align__(16) float g_boxes[NANCH*4];
__device__ float g_key1[NPAD1];
__device__ int   g_idx1[NPAD1];
__device__ __align__(16) float g_sbox1[NANCH*4];
__device__ unsigned long long g_mask1[(size_t)NANCH*NBW1];
__device__ int   g_keep1[KP];
__device__ __align__(16) float g_prop4[KP*4];
__device__ __align__(16) float g_nbox[KP*4];
__device__ __align__(16) float g_flat[(size_t)KP*FK];
__device__ __align__(16) float g_h1[KP*1024];
__device__ __align__(16) float g_h2[KP*1024];
__device__ float g_rsc[KP];
__device__ __align__(16) float g_dets[KP*4];
__device__ float g_key2[NPAD2];
__device__ int   g_idx2[NPAD2];
__device__ __align__(16) float g_sdet[KP*4];
__device__ unsigned long long g_mask2[(size_t)KP*NBW2];
__device__ int   g_keep2[KP];
__device__ int   g_nk2;

// fast-math-immune, correctly-rounded fp32 exp
__device__ __forceinline__ float exp_strict(float x){
    return (float)exp((double)x);
}

// exact mirror of jax.nn.softmax([l0,l1])[1] in fp32
__device__ __forceinline__ float softmax1(float l0, float l1){
    float m = fmaxf(l0, l1);
    float e0 = exp_strict(__fsub_rn(l0, m));
    float e1 = exp_strict(__fsub_rn(l1, m));
    return __fdiv_rn(e1, __fadd_rn(e0, e1));
}

// ---------------- weight permutes ----------------
__global__ void k_transpose(const float* __restrict__ src, int K, int which){
    float* dst = which ? g_rwT : g_bbT;
    int t = blockIdx.x*blockDim.x + threadIdx.x;
    if (t < K*128){
        int i = t >> 7, c = t & 127;
        dst[t] = src[c*K + i];
    }
}

__global__ void __launch_bounds__(256) k_tfc1(const float* __restrict__ w){
    __shared__ float s[FK];
    int h = blockIdx.x;
    const float* src = w + (size_t)h*FK;
    for (int t = threadIdx.x; t < FK; t += 256) s[t] = src[t];
    __syncthreads();
    float* dst = g_fc1wP + (size_t)h*FK;
    for (int t = threadIdx.x; t < FK; t += 256){
        int p = t >> 7, c = t & 127;
        dst[t] = s[c*49 + p];
    }
}

__global__ void k_init(){
    int t = blockIdx.x*blockDim.x + threadIdx.x;
    if (t < NPAD1 - NANCH){ g_key1[NANCH+t] = -1.f; g_idx1[NANCH+t] = 0x7fffffff; }
    if (t < NPAD2 - KP)   { g_key2[KP+t]    = -1.f; g_idx2[KP+t]    = 0x7fffffff; }
}

// ---------------- conv1: 3->128, 16x16 stride16 VALID, relu (fp64 accum — REQUIRED) ----------------
__global__ void __launch_bounds__(128) k_conv1(const float* __restrict__ x, const float* __restrict__ bias){
    __shared__ float sp[4*768];
    int gy  = blockIdx.x >> 3;
    int gx0 = (blockIdx.x & 7) * 4;
    int tid = threadIdx.x;
    for (int e = tid; e < 3072; e += 128){
        int spx = e / 768, i = e % 768;
        int ci = i >> 8, rr = i & 255, ky = rr >> 4, kx = rr & 15;
        sp[e] = x[ci*(512*512) + (gy*16+ky)*512 + (gx0+spx)*16 + kx];
    }
    __syncthreads();
    double a0=0, a1=0, a2=0, a3=0;
    for (int i = 0; i < 768; i++){
        double w = (double)g_bbT[i*128 + tid];
        a0 = fma((double)sp[i],      w, a0);
        a1 = fma((double)sp[768+i],  w, a1);
        a2 = fma((double)sp[1536+i], w, a2);
        a3 = fma((double)sp[2304+i], w, a3);
    }
    float b = bias[tid];
    int base = (gy*32 + gx0)*128 + tid;
    g_featT[base      ] = fmaxf(__fadd_rn((float)a0, b), 0.f);
    g_featT[base + 128] = fmaxf(__fadd_rn((float)a1, b), 0.f);
    g_featT[base + 256] = fmaxf(__fadd_rn((float)a2, b), 0.f);
    g_featT[base + 384] = fmaxf(__fadd_rn((float)a3, b), 0.f);
}

// ---------------- conv2: 3x3 SAME 128->128, relu (fp64 accum — REQUIRED) ----------------
__global__ void __launch_bounds__(128) k_conv2(const float* __restrict__ bias){
    __shared__ float sp[18*128];
    int gy  = blockIdx.x >> 3;
    int gx0 = (blockIdx.x & 7) * 4;
    int tid = threadIdx.x;
    for (int e = tid; e < 18*128; e += 128){
        int pix = e >> 7, ci = e & 127;
        int ky = pix / 6, sx = pix % 6;
        int iy = gy + ky - 1, ix = gx0 + sx - 1;
        float v = 0.f;
        if (iy >= 0 && iy < 32 && ix >= 0 && ix < 32) v = g_featT[(iy*32+ix)*128 + ci];
        sp[e] = v;
    }
    __syncthreads();
    double a0=0, a1=0, a2=0, a3=0;
    int i = 0;
    for (int ci = 0; ci < 128; ci++){
        #pragma unroll
        for (int ky = 0; ky < 3; ky++){
            #pragma unroll
            for (int kx = 0; kx < 3; kx++){
                double w = (double)g_rwT[i*128 + tid];
                int base = (ky*6+kx)*128 + ci;
                a0 = fma((double)sp[base      ], w, a0);
                a1 = fma((double)sp[base + 128], w, a1);
                a2 = fma((double)sp[base + 256], w, a2);
                a3 = fma((double)sp[base + 384], w, a3);
                i++;
            }
        }
    }
    float b = bias[tid];
    int ob = (gy*32+gx0)*128 + tid;
    g_hT[ob      ] = fmaxf(__fadd_rn((float)a0, b), 0.f);
    g_hT[ob + 128] = fmaxf(__fadd_rn((float)a1, b), 0.f);
    g_hT[ob + 256] = fmaxf(__fadd_rn((float)a2, b), 0.f);
    g_hT[ob + 384] = fmaxf(__fadd_rn((float)a3, b), 0.f);
}

// ---------------- RPN heads + softmax + anchors + decode + clip (fp64 dots — REQUIRED) ----------------
__global__ void __launch_bounds__(64) k_rpn(const float* __restrict__ cw, const float* __restrict__ cb,
                                            const float* __restrict__ rw, const float* __restrict__ rb,
                                            float* __restrict__ out){
    __shared__ float sh[128];
    __shared__ float sd[54];
    int pix = blockIdx.x;
    int tid = threadIdx.x;
    sh[tid]      = g_hT[pix*128 + tid];
    sh[tid + 64] = g_hT[pix*128 + tid + 64];
    __syncthreads();
    if (tid < 54){
        const float* wrow = (tid < 18) ? (cw + tid*128) : (rw + (tid-18)*128);
        float bb = (tid < 18) ? cb[tid] : rb[tid-18];
        double acc = 0.0;
        for (int c = 0; c < 128; c++) acc = fma((double)sh[c], (double)wrow[c], acc);
        sd[tid] = __fadd_rn((float)acc, bb);
    }
    __syncthreads();
    if (tid < 9){
        int a = tid;
        int y = pix >> 5, x = pix & 31;
        int n = pix*9 + a;
        float l0 = sd[2*a], l1 = sd[2*a+1];
        out[O_RPNL + n*2+0] = l0; out[O_RPNL + n*2+1] = l1;
        float d0 = sd[18+4*a+0], d1 = sd[18+4*a+1], d2 = sd[18+4*a+2], d3 = sd[18+4*a+3];
        out[O_RPND + n*4+0]=d0; out[O_RPND + n*4+1]=d1;
        out[O_RPND + n*4+2]=d2; out[O_RPND + n*4+3]=d3;
        const float scv[3] = {32.f, 64.f, 128.f};
        const float rv[3]  = {0.5f, 1.f, 2.f};
        int si = a/3, ri = a%3;
        float sr = __fsqrt_rn(rv[ri]);
        float ws = __fdiv_rn(scv[si], sr);
        float hs = __fmul_rn(scv[si], sr);
        float cx = __fmul_rn(__fadd_rn((float)x, 0.5f), 16.f);
        float cy = __fmul_rn(__fadd_rn((float)y, 0.5f), 16.f);
        float W2 = __fmul_rn(ws, 0.5f);
        float H2 = __fmul_rn(hs, 0.5f);
        float ax1 = __fsub_rn(cx, W2), ay1 = __fsub_rn(cy, H2);
        float ax2 = __fadd_rn(cx, W2), ay2 = __fadd_rn(cy, H2);
        out[O_ANCH + n*4+0]=ax1; out[O_ANCH + n*4+1]=ay1;
        out[O_ANCH + n*4+2]=ax2; out[O_ANCH + n*4+3]=ay2;
        float w = __fadd_rn(__fsub_rn(ax2, ax1), 1.f);
        float h = __fadd_rn(__fsub_rn(ay2, ay1), 1.f);
        float ccx = __fadd_rn(ax1, __fmul_rn(0.5f, w));
        float ccy = __fadd_rn(ay1, __fmul_rn(0.5f, h));
        float pcx = __fadd_rn(__fmul_rn(d0, w), ccx);
        float pcy = __fadd_rn(__fmul_rn(d1, h), ccy);
        float pw = __fmul_rn(exp_strict(d2), w);
        float ph = __fmul_rn(exp_strict(d3), h);
        float hw = __fmul_rn(0.5f, pw), hh = __fmul_rn(0.5f, ph);
        g_boxes[n*4+0] = fminf(fmaxf(__fsub_rn(pcx, hw), 0.f), 511.f);
        g_boxes[n*4+1] = fminf(fmaxf(__fsub_rn(pcy, hh), 0.f), 511.f);
        g_boxes[n*4+2] = fminf(fmaxf(__fadd_rn(pcx, hw), 0.f), 511.f);
        g_boxes[n*4+3] = fminf(fmaxf(__fadd_rn(pcy, hh), 0.f), 511.f);
        g_key1[n] = softmax1(l0, l1);
        g_idx1[n] = n;
    }
}

// ---------------- hybrid bitonic sort (desc score, tie idx asc) ----------------
__device__ __forceinline__ bool cmp_before(float ka, int ia, float kb, int ib){
    return (ka > kb) || (ka == kb && ia < ib);
}

__global__ void __launch_bounds__(1024) k_sort_local(float* __restrict__ key, int* __restrict__ idx){
    __shared__ float sk[2048];
    __shared__ int   si[2048];
    int base = blockIdx.x * 2048;
    for (int t = threadIdx.x; t < 2048; t += 1024){ sk[t] = key[base+t]; si[t] = idx[base+t]; }
    __syncthreads();
    for (int kk = 2; kk <= 2048; kk <<= 1){
        for (int j = kk >> 1; j > 0; j >>= 1){
            for (int t = threadIdx.x; t < 2048; t += 1024){
                int p = t ^ j;
                if (p > t){
                    bool up = (((base + t) & kk) == 0);
                    float ka = sk[t], kb = sk[p];
                    int ia = si[t], ib = si[p];
                    bool sw = up ? cmp_before(kb, ib, ka, ia) : cmp_before(ka, ia, kb, ib);
                    if (sw){ sk[t]=kb; si[t]=ib; sk[p]=ka; si[p]=ia; }
                }
            }
            __syncthreads();
        }
    }
    for (int t = threadIdx.x; t < 2048; t += 1024){ key[base+t] = sk[t]; idx[base+t] = si[t]; }
}

__global__ void __launch_bounds__(256) k_sort_global(float* __restrict__ key, int* __restrict__ idx,
                                                     int kk, int j, int npad){
    int i = blockIdx.x*256 + threadIdx.x;
    int p = i ^ j;
    if (i < npad && p > i && p < npad){
        bool up = ((i & kk) == 0);
        float ka = key[i], kb = key[p];
        int ia = idx[i], ib = idx[p];
        bool sw = up ? cmp_before(kb, ib, ka, ia) : cmp_before(ka, ia, kb, ib);
        if (sw){ key[i]=kb; idx[i]=ib; key[p]=ka; idx[p]=ia; }
    }
}

__global__ void __launch_bounds__(1024) k_merge_local(float* __restrict__ key, int* __restrict__ idx, int kk){
    __shared__ float sk[2048];
    __shared__ int   si[2048];
    int base = blockIdx.x * 2048;
    for (int t = threadIdx.x; t < 2048; t += 1024){ sk[t] = key[base+t]; si[t] = idx[base+t]; }
    __syncthreads();
    for (int j = 1024; j > 0; j >>= 1){
        for (int t = threadIdx.x; t < 2048; t += 1024){
            int p = t ^ j;
            if (p > t){
                bool up = (((base + t) & kk) == 0);
                float ka = sk[t], kb = sk[p];
                int ia = si[t], ib = si[p];
                bool sw = up ? cmp_before(kb, ib, ka, ia) : cmp_before(ka, ia, kb, ib);
                if (sw){ sk[t]=kb; si[t]=ib; sk[p]=ka; si[p]=ia; }
            }
        }
        __syncthreads();
    }
    for (int t = threadIdx.x; t < 2048; t += 1024){ key[base+t] = sk[t]; idx[base+t] = si[t]; }
}

// ---------------- gathers ----------------
__global__ void k_gather1(){
    int i = blockIdx.x*blockDim.x + threadIdx.x;
    if (i < NANCH){
        int id = g_idx1[i];
        ((float4*)g_sbox1)[i] = ((const float4*)g_boxes)[id];
    }
}

__global__ void k_gather2(){
    int i = blockIdx.x*blockDim.x + threadIdx.x;
    if (i < KP){
        int id = g_idx2[i];
        ((float4*)g_sdet)[i] = ((const float4*)g_dets)[id];
    }
}

// ---------------- NMS mask build: upper-triangle tiles only, div-skip ----------------
// Lower-triangle mask words stay unwritten; the scans never consume them
// (the active word at group g is always >= every visited row's group).
__global__ void __launch_bounds__(64) k_mask(const float* __restrict__ sbox, int n, int nbw,
                                             unsigned long long* __restrict__ mask, float thr){
    // linear block -> (ib, jb) with jb >= ib. S(ib) = ib*nbw - ib*(ib-1)/2
    int t = blockIdx.x;
    int ib = (int)(((2.0*nbw + 1.0) - sqrt((2.0*nbw + 1.0)*(2.0*nbw + 1.0) - 8.0*(double)t)) * 0.5);
    if (ib < 0) ib = 0;
    while (ib > 0 && ib*nbw - ib*(ib-1)/2 > t) ib--;
    while ((ib+1)*nbw - (ib+1)*ib/2 <= t) ib++;
    int jb = ib + (t - (ib*nbw - ib*(ib-1)/2));

    __shared__ float4 cb[64];
    __shared__ float  ca[64];
    int cj = jb*64 + threadIdx.x;
    if (cj < n){
        float4 b = ((const float4*)sbox)[cj];
        cb[threadIdx.x] = b;
        ca[threadIdx.x] = __fmul_rn(__fadd_rn(__fsub_rn(b.z,b.x),1.f), __fadd_rn(__fsub_rn(b.w,b.y),1.f));
    } else {
        cb[threadIdx.x] = make_float4(0,0,0,0);
        ca[threadIdx.x] = 1.f;
    }
    __syncthreads();
    int r = ib*64 + threadIdx.x;
    if (r >= n) return;
    float4 rb = ((const float4*)sbox)[r];
    float ra = __fmul_rn(__fadd_rn(__fsub_rn(rb.z,rb.x),1.f), __fadd_rn(__fsub_rn(rb.w,rb.y),1.f));
    unsigned long long m = 0;
    int cols = n - jb*64; if (cols > 64) cols = 64;
    if (ib == jb){
        for (int b = 0; b < cols; b++){
            int j = jb*64 + b;
            if (j > r){
                float4 o = cb[b];
                float xx1 = fmaxf(rb.x, o.x), yy1 = fmaxf(rb.y, o.y);
                float xx2 = fminf(rb.z, o.z), yy2 = fminf(rb.w, o.w);
                float iw = fmaxf(__fadd_rn(__fsub_rn(xx2,xx1),1.f), 0.f);
                float ih = fmaxf(__fadd_rn(__fsub_rn(yy2,yy1),1.f), 0.f);
                float inter = __fmul_rn(iw, ih);
                if (inter > 0.f){
                    float iou = __fdiv_rn(inter, __fsub_rn(__fadd_rn(ra, ca[b]), inter));
                    if (iou > thr) m |= (1ULL << b);
                }
            }
        }
    } else {
        for (int b = 0; b < cols; b++){
            float4 o = cb[b];
            float xx1 = fmaxf(rb.x, o.x), yy1 = fmaxf(rb.y, o.y);
            float xx2 = fminf(rb.z, o.z), yy2 = fminf(rb.w, o.w);
            float iw = fmaxf(__fadd_rn(__fsub_rn(xx2,xx1),1.f), 0.f);
            float ih = fmaxf(__fadd_rn(__fsub_rn(yy2,yy1),1.f), 0.f);
            float inter = __fmul_rn(iw, ih);
            if (inter > 0.f){
                float iou = __fdiv_rn(inter, __fsub_rn(__fadd_rn(ra, ca[b]), inter));
                if (iou > thr) m |= (1ULL << b);
            }
        }
    }
    mask[(size_t)r*nbw + jb] = m;
}

// ---------------- NMS scan 1: cached current-word, shfl only on keep ----------------
__global__ void k_scan1(){
    int lane = threadIdx.x;
    unsigned long long remv[5] = {0,0,0,0,0};
    unsigned long long buf[8][5];
    int cnt = 0;
    bool done = false;
    #pragma unroll
    for (int d = 0; d < 8; d++)
        #pragma unroll
        for (int q = 0; q < 5; q++){
            int wq = q*32 + lane;
            buf[d][q] = (wq < NBW1) ? g_mask1[(size_t)d*NBW1 + wq] : 0ULL;
        }
    for (int g = 0; g < NANCH/64 && !done; g++){
        int slot = g >> 5, owner = g & 31;
        unsigned long long myw = slot==0?remv[0]:slot==1?remv[1]:slot==2?remv[2]:slot==3?remv[3]:remv[4];
        unsigned long long cur = __shfl_sync(FULLM, myw, owner);
        #pragma unroll
        for (int b = 0; b < 64; b++){
            if (!done){
                int i = g*64 + b;
                const int d = b & 7;
                if (!((cur >> b) & 1ULL)){
                    if (lane == 0 && cnt < KP) g_keep1[cnt] = g_idx1[i];
                    cnt++;
                    if (cnt >= KP){ done = true; }
                    else {
                        #pragma unroll
                        for (int q = 0; q < 5; q++) remv[q] |= buf[d][q];
                        unsigned long long dw = slot==0?buf[d][0]:slot==1?buf[d][1]:slot==2?buf[d][2]:slot==3?buf[d][3]:buf[d][4];
                        cur |= __shfl_sync(FULLM, dw, owner);
                    }
                }
                if (!done){
                    int ni = i + 8;
                    #pragma unroll
                    for (int q = 0; q < 5; q++){
                        int wq = q*32 + lane;
                        buf[d][q] = (ni < NANCH && wq < NBW1) ? g_mask1[(size_t)ni*NBW1 + wq] : 0ULL;
                    }
                }
            }
        }
    }
    for (int t = cnt + lane; t < KP; t += 32) g_keep1[t] = 0;
}

// ---------------- NMS scan 2 ----------------
__global__ void k_scan2(){
    int lane = threadIdx.x;
    unsigned long long remv = 0;
    unsigned long long buf[8];
    int cnt = 0;
    bool done = false;
    #pragma unroll
    for (int d = 0; d < 8; d++)
        buf[d] = g_mask2[(size_t)d*NBW2 + lane];
    for (int g = 0; g < (KP + 63)/64 && !done; g++){
        unsigned long long cur = __shfl_sync(FULLM, remv, g);
        #pragma unroll
        for (int b = 0; b < 64; b++){
            if (!done){
                int i = g*64 + b;
                const int d = b & 7;
                if (i < KP){
                    if (!((cur >> b) & 1ULL)){
                        if (lane == 0 && cnt < KP) g_keep2[cnt] = g_idx2[i];
                        cnt++;
                        if (cnt >= KP){ done = true; }
                        else {
                            remv |= buf[d];
                            cur |= __shfl_sync(FULLM, buf[d], g);
                        }
                    }
                    if (!done){
                        int ni = i + 8;
                        buf[d] = (ni < KP) ? g_mask2[(size_t)ni*NBW2 + lane] : 0ULL;
                    }
                }
            }
        }
    }
    if (lane == 0) g_nk2 = cnt;
    for (int t = cnt + lane; t < KP; t += 32) g_keep2[t] = 0;
}

// ---------------- proposals ----------------
__global__ void k_props(float* __restrict__ out){
    int i = blockIdx.x*blockDim.x + threadIdx.x;
    if (i < KP){
        int id = g_keep1[i];
        float4 b = ((const float4*)g_boxes)[id];
        out[O_PROPS + i*4+0] = b.x; out[O_PROPS + i*4+1] = b.y;
        out[O_PROPS + i*4+2] = b.z; out[O_PROPS + i*4+3] = b.w;
        ((float4*)g_prop4)[i] = b;
        g_nbox[i*4+0] = __fdiv_rn(b.y, 511.f);
        g_nbox[i*4+1] = __fdiv_rn(b.x, 511.f);
        g_nbox[i*4+2] = __fdiv_rn(b.w, 511.f);
        g_nbox[i*4+3] = __fdiv_rn(b.z, 511.f);
    }
}

// ---------------- crop + bilinear + 2x2 maxpool ----------------
__global__ void __launch_bounds__(256) k_crop(){
    int k = blockIdx.x;
    int warp = threadIdx.x >> 5, lane = threadIdx.x & 31;
    float y1 = g_nbox[k*4+0], x1 = g_nbox[k*4+1], y2 = g_nbox[k*4+2], x2 = g_nbox[k*4+3];
    float dy = __fsub_rn(y2, y1), dx = __fsub_rn(x2, x1);
    int c4 = lane*4;
    const float4* f = (const float4*)g_featT;
    for (int p = warp; p < 49; p += 8){
        int oi = p/7, oj = p%7;
        float4 acc = make_float4(-1e30f,-1e30f,-1e30f,-1e30f);
        #pragma unroll
        for (int di = 0; di < 2; di++){
            #pragma unroll
            for (int dj = 0; dj < 2; dj++){
                int ti = 2*oi+di, tj = 2*oj+dj;
                float ty = __fdiv_rn((float)ti, 13.f);
                float tx = __fdiv_rn((float)tj, 13.f);
                float ys = __fmul_rn(__fadd_rn(y1, __fmul_rn(ty, dy)), 31.f);
                float xs = __fmul_rn(__fadd_rn(x1, __fmul_rn(tx, dx)), 31.f);
                int y0 = min(max((int)floorf(ys), 0), 31);
                int y1i = min(y0+1, 31);
                int x0 = min(max((int)floorf(xs), 0), 31);
                int x1i = min(x0+1, 31);
                float wy = __fsub_rn(ys, (float)y0);
                float wx = __fsub_rn(xs, (float)x0);
                float omwx = __fsub_rn(1.f, wx), omwy = __fsub_rn(1.f, wy);
                float4 f00 = f[((y0*32+x0)*128 + c4) >> 2];
                float4 f01 = f[((y0*32+x1i)*128 + c4) >> 2];
                float4 f10 = f[((y1i*32+x0)*128 + c4) >> 2];
                float4 f11 = f[((y1i*32+x1i)*128 + c4) >> 2];
                #pragma unroll
                for (int e = 0; e < 4; e++){
                    float a00 = (&f00.x)[e], a01 = (&f01.x)[e];
                    float a10 = (&f10.x)[e], a11 = (&f11.x)[e];
                    float top = __fadd_rn(__fmul_rn(a00, omwx), __fmul_rn(a01, wx));
                    float bot = __fadd_rn(__fmul_rn(a10, omwx), __fmul_rn(a11, wx));
                    float val = __fadd_rn(__fmul_rn(top, omwy), __fmul_rn(bot, wy));
                    (&acc.x)[e] = fmaxf((&acc.x)[e], val);
                }
            }
        }
        ((float4*)g_flat)[((size_t)k*FK + p*128 + c4) >> 2] = acc;
    }
}

// ---------------- fp32 SIMT GEMM: C = relu(A @ B^T + bias) ----------------
#define GP 132
__global__ void __launch_bounds__(256) k_gemm(const float* __restrict__ A, const float* __restrict__ B,
                                              const float* __restrict__ bias, float* __restrict__ Cmat,
                                              int M, int N, int K){
    __shared__ float As[2][16][GP];
    __shared__ float Bs[2][16][GP];
    int tid = threadIdx.x;
    int tx = tid & 15, ty = tid >> 4;
    int mbase = blockIdx.y*128, nbase = blockIdx.x*128;
    float acc[8][8];
    #pragma unroll
    for (int r = 0; r < 8; r++)
        #pragma unroll
        for (int q = 0; q < 8; q++) acc[r][q] = 0.f;

    int r0 = tid >> 2,          c0 = (tid & 3) * 4;
    int r1 = (tid + 256) >> 2,  c1 = ((tid + 256) & 3) * 4;
    const float* Ap0 = A + (size_t)(mbase + r0)*K + c0;
    const float* Ap1 = A + (size_t)(mbase + r1)*K + c1;
    const float* Bp0 = B + (size_t)(nbase + r0)*K + c0;
    const float* Bp1 = B + (size_t)(nbase + r1)*K + c1;
    bool av0 = (mbase + r0) < M, av1 = (mbase + r1) < M;

    float4 a0 = av0 ? *(const float4*)Ap0 : make_float4(0,0,0,0);
    float4 a1 = av1 ? *(const float4*)Ap1 : make_float4(0,0,0,0);
    float4 b0 = *(const float4*)Bp0;
    float4 b1 = *(const float4*)Bp1;
    As[0][c0+0][r0]=a0.x; As[0][c0+1][r0]=a0.y; As[0][c0+2][r0]=a0.z; As[0][c0+3][r0]=a0.w;
    As[0][c1+0][r1]=a1.x; As[0][c1+1][r1]=a1.y; As[0][c1+2][r1]=a1.z; As[0][c1+3][r1]=a1.w;
    Bs[0][c0+0][r0]=b0.x; Bs[0][c0+1][r0]=b0.y; Bs[0][c0+2][r0]=b0.z; Bs[0][c0+3][r0]=b0.w;
    Bs[0][c1+0][r1]=b1.x; Bs[0][c1+1][r1]=b1.y; Bs[0][c1+2][r1]=b1.z; Bs[0][c1+3][r1]=b1.w;
    __syncthreads();

    int nIter = K / 16;
    for (int it = 0; it < nIter; it++){
        int buf = it & 1;
        float4 na0, na1, nb0, nb1;
        if (it + 1 < nIter){
            int koff = (it+1)*16;
            na0 = av0 ? *(const float4*)(Ap0 + koff) : make_float4(0,0,0,0);
            na1 = av1 ? *(const float4*)(Ap1 + koff) : make_float4(0,0,0,0);
            nb0 = *(const float4*)(Bp0 + koff);
            nb1 = *(const float4*)(Bp1 + koff);
        }
        #pragma unroll
        for (int kk = 0; kk < 16; kk++){
            float ar[8], br[8];
            *(float4*)(ar)   = *(const float4*)&As[buf][kk][ty*8];
            *(float4*)(ar+4) = *(const float4*)&As[buf][kk][ty*8+4];
            *(float4*)(br)   = *(const float4*)&Bs[buf][kk][tx*8];
            *(float4*)(br+4) = *(const float4*)&Bs[buf][kk][tx*8+4];
            #pragma unroll
            for (int r = 0; r < 8; r++)
                #pragma unroll
                for (int q = 0; q < 8; q++)
                    acc[r][q] = fmaf(ar[r], br[q], acc[r][q]);
        }
        if (it + 1 < nIter){
            int nb = buf ^ 1;
            // store targets the buffer whose last readers finished before the
            // previous sync -> single sync per iteration suffices
            As[nb][c0+0][r0]=na0.x; As[nb][c0+1][r0]=na0.y; As[nb][c0+2][r0]=na0.z; As[nb][c0+3][r0]=na0.w;
            As[nb][c1+0][r1]=na1.x; As[nb][c1+1][r1]=na1.y; As[nb][c1+2][r1]=na1.z; As[nb][c1+3][r1]=na1.w;
            Bs[nb][c0+0][r0]=nb0.x; Bs[nb][c0+1][r0]=nb0.y; Bs[nb][c0+2][r0]=nb0.z; Bs[nb][c0+3][r0]=nb0.w;
            Bs[nb][c1+0][r1]=nb1.x; Bs[nb][c1+1][r1]=nb1.y; Bs[nb][c1+2][r1]=nb1.z; Bs[nb][c1+3][r1]=nb1.w;
            __syncthreads();
        }
    }
    #pragma unroll
    for (int r = 0; r < 8; r++){
        int row = mbase + ty*8 + r;
        if (row < M){
            #pragma unroll
            for (int q = 0; q < 8; q++){
                int col = nbase + tx*8 + q;
                Cmat[(size_t)row*N + col] = fmaxf(__fadd_rn(acc[r][q], bias[col]), 0.f);
            }
        }
    }
}

// ---------------- RCNN heads + decode2 (fp64 dots — decision path) ----------------
__global__ void __launch_bounds__(192) k_heads(const float* __restrict__ cw, const float* __restrict__ cb,
                                               const float* __restrict__ rw, const float* __restrict__ rb,
                                               float* __restrict__ out){
    __shared__ float sd[6];
    int k = blockIdx.x;
    int warp = threadIdx.x >> 5, lane = threadIdx.x & 31;
    const float4* h4 = (const float4*)(g_h2 + (size_t)k*1024);
    const float4* w4 = (const float4*)((warp < 2) ? (cw + warp*1024) : (rw + (warp-2)*1024));
    double acc = 0.0;
    #pragma unroll
    for (int q = 0; q < 8; q++){
        float4 a = h4[lane + q*32], b = w4[lane + q*32];
        acc = fma((double)a.x, (double)b.x, acc);
        acc = fma((double)a.y, (double)b.y, acc);
        acc = fma((double)a.z, (double)b.z, acc);
        acc = fma((double)a.w, (double)b.w, acc);
    }
    #pragma unroll
    for (int o = 16; o; o >>= 1) acc += __shfl_xor_sync(FULLM, acc, o);
    if (lane == 0) sd[warp] = __fadd_rn((float)acc, (warp < 2) ? cb[warp] : rb[warp-2]);
    __syncthreads();
    if (threadIdx.x == 0){
        float l0 = sd[0], l1 = sd[1];
        out[O_RCL + k*2+0] = l0; out[O_RCL + k*2+1] = l1;
        float d0 = sd[2], d1 = sd[3], d2 = sd[4], d3 = sd[5];
        out[O_RCD + k*4+0]=d0; out[O_RCD + k*4+1]=d1;
        out[O_RCD + k*4+2]=d2; out[O_RCD + k*4+3]=d3;
        float score = softmax1(l0, l1);
        float4 pr = ((const float4*)g_prop4)[k];
        float w = __fadd_rn(__fsub_rn(pr.z, pr.x), 1.f);
        float h = __fadd_rn(__fsub_rn(pr.w, pr.y), 1.f);
        float ccx = __fadd_rn(pr.x, __fmul_rn(0.5f, w));
        float ccy = __fadd_rn(pr.y, __fmul_rn(0.5f, h));
        float pcx = __fadd_rn(__fmul_rn(d0, w), ccx);
        float pcy = __fadd_rn(__fmul_rn(d1, h), ccy);
        float pw = __fmul_rn(exp_strict(d2), w);
        float ph = __fmul_rn(exp_strict(d3), h);
        float hw = __fmul_rn(0.5f, pw), hh = __fmul_rn(0.5f, ph);
        float4 dt;
        dt.x = fminf(fmaxf(__fsub_rn(pcx, hw), 0.f), 511.f);
        dt.y = fminf(fmaxf(__fsub_rn(pcy, hh), 0.f), 511.f);
        dt.z = fminf(fmaxf(__fadd_rn(pcx, hw), 0.f), 511.f);
        dt.w = fminf(fmaxf(__fadd_rn(pcy, hh), 0.f), 511.f);
        ((float4*)g_dets)[k] = dt;
        g_rsc[k] = score;
        g_key2[k] = score;
        g_idx2[k] = k;
    }
}

// ---------------- final outputs ----------------
__global__ void k_final(float* __restrict__ out){
    int i = blockIdx.x*blockDim.x + threadIdx.x;
    if (i < KP){
        float m = (i < g_nk2) ? 1.f : 0.f;
        int id = g_keep2[i];
        float4 d = ((const float4*)g_dets)[id];
        out[O_DETS + i*4+0] = d.x*m; out[O_DETS + i*4+1] = d.y*m;
        out[O_DETS + i*4+2] = d.z*m; out[O_DETS + i*4+3] = d.w*m;
        out[O_SC + i] = g_rsc[id]*m;
    }
}

// ---------------- launch ----------------
extern "C" void kernel_launch(void* const* d_in, const int* in_sizes, int n_in,
                              void* d_out, int out_size){
    const float* x        = (const float*)d_in[0];
    const float* bb_w     = (const float*)d_in[1];
    const float* bb_b     = (const float*)d_in[2];
    const float* rpn_w    = (const float*)d_in[3];
    const float* rpn_b    = (const float*)d_in[4];
    const float* rpn_cls_w= (const float*)d_in[5];
    const float* rpn_cls_b= (const float*)d_in[6];
    const float* rpn_reg_w= (const float*)d_in[7];
    const float* rpn_reg_b= (const float*)d_in[8];
    const float* fc1_w    = (const float*)d_in[9];
    const float* fc1_b    = (const float*)d_in[10];
    const float* fc2_w    = (const float*)d_in[11];
    const float* fc2_b    = (const float*)d_in[12];
    const float* cls_w    = (const float*)d_in[13];
    const float* cls_b    = (const float*)d_in[14];
    const float* reg_w    = (const float*)d_in[15];
    const float* reg_b    = (const float*)d_in[16];
    float* out = (float*)d_out;

    float *p_key1, *p_key2, *p_sbox1, *p_sdet, *p_flat, *p_fc1wP, *p_h1, *p_h2;
    int *p_idx1, *p_idx2;
    unsigned long long *p_mask1, *p_mask2;
    cudaGetSymbolAddress((void**)&p_key1,  g_key1);
    cudaGetSymbolAddress((void**)&p_idx1,  g_idx1);
    cudaGetSymbolAddress((void**)&p_key2,  g_key2);
    cudaGetSymbolAddress((void**)&p_idx2,  g_idx2);
    cudaGetSymbolAddress((void**)&p_sbox1, g_sbox1);
    cudaGetSymbolAddress((void**)&p_sdet,  g_sdet);
    cudaGetSymbolAddress((void**)&p_mask1, g_mask1);
    cudaGetSymbolAddress((void**)&p_mask2, g_mask2);
    cudaGetSymbolAddress((void**)&p_flat,  g_flat);
    cudaGetSymbolAddress((void**)&p_fc1wP, g_fc1wP);
    cudaGetSymbolAddress((void**)&p_h1,    g_h1);
    cudaGetSymbolAddress((void**)&p_h2,    g_h2);

    k_transpose<<<(768*128+255)/256, 256>>>(bb_w, 768, 0);
    k_transpose<<<(1152*128+255)/256, 256>>>(rpn_w, 1152, 1);
    k_tfc1<<<1024, 256>>>(fc1_w);
    k_init<<<32, 256>>>();

    k_conv1<<<256, 128>>>(x, bb_b);
    k_conv2<<<256, 128>>>(rpn_b);
    k_rpn<<<1024, 64>>>(rpn_cls_w, rpn_cls_b, rpn_reg_w, rpn_reg_b, out);

    // hybrid bitonic sort over 16384 (desc score, tie idx asc)
    k_sort_local<<<8, 1024>>>(p_key1, p_idx1);
    for (int kk = 4096; kk <= NPAD1; kk <<= 1){
        for (int j = kk >> 1; j >= 2048; j >>= 1)
            k_sort_global<<<NPAD1/256, 256>>>(p_key1, p_idx1, kk, j, NPAD1);
        k_merge_local<<<8, 1024>>>(p_key1, p_idx1, kk);
    }

    k_gather1<<<(NANCH+255)/256, 256>>>();
    k_mask<<<NBW1*(NBW1+1)/2, 64>>>(p_sbox1, NANCH, NBW1, p_mask1, 0.5f);
    k_scan1<<<1, 32>>>();
    k_props<<<(KP+255)/256, 256>>>(out);
    k_crop<<<KP, 256>>>();

    {
        dim3 g1(8, 16);
        k_gemm<<<g1, 256>>>(p_flat, p_fc1wP, fc1_b, p_h1, KP, 1024, FK);
        k_gemm<<<g1, 256>>>(p_h1, fc2_w, fc2_b, p_h2, KP, 1024, 1024);
    }
    k_heads<<<KP, 192>>>(cls_w, cls_b, reg_w, reg_b, out);

    k_sort_local<<<1, 1024>>>(p_key2, p_idx2);

    k_gather2<<<(KP+255)/256, 256>>>();
    k_mask<<<NBW2*(NBW2+1)/2, 64>>>(p_sdet, KP, NBW2, p_mask2, 0.3f);
    k_scan2<<<1, 32>>>();
    k_final<<<(KP+255)/256, 256>>>(out);
}

// round 12
// speedup vs baseline: 1.4764x; 1.4764x over previous
#include <cuda_runtime.h>
#include <math.h>

#define NANCH 9216
#define NPAD1 16384
#define NBW1  144
#define KP    2000
#define NPAD2 2048
#define NBW2  32
#define FK    6272

// output offsets (floats)
#define O_RPNL  0
#define O_RPND  18432
#define O_PROPS 55296
#define O_ANCH  63296
#define O_RCL   100160
#define O_RCD   104160
#define O_DETS  112160
#define O_SC    120160

// ---------------- device scratch ----------------
__device__ __align__(16) float g_featT[32*32*128];
__device__ __align__(16) float g_hT[32*32*128];
__device__ __align__(16) float g_bbT[768*128];
__device__ __align__(16) float g_rwT[1152*128];
__device__ __align__(16) float g_fc1wP[1024*FK];
__device__ __align__(16) float g_boxes[NANCH*4];
__device__ float g_key1[NPAD1];
__device__ int   g_idx1[NPAD1];
__device__ __align__(16) float g_sbox1[NANCH*4];
__device__ unsigned long long g_mask1[(size_t)NANCH*NBW1];
__device__ int   g_keep1[KP];
__device__ __align__(16) float g_prop4[KP*4];
__device__ __align__(16) float g_nbox[KP*4];
__device__ __align__(16) float g_flat[(size_t)KP*FK];
__device__ __align__(16) float g_h1[KP*1024];
__device__ __align__(16) float g_h2[KP*1024];
__device__ float g_rsc[KP];
__device__ __align__(16) float g_dets[KP*4];
__device__ float g_key2[NPAD2];
__device__ int   g_idx2[NPAD2];
__device__ __align__(16) float g_sdet[KP*4];
__device__ unsigned long long g_mask2[(size_t)KP*NBW2];
__device__ int   g_keep2[KP];
__device__ int   g_nk2;

// fast-math-immune, correctly-rounded fp32 exp (double exp is never remapped)
__device__ __forceinline__ float exp_strict(float x){
    return (float)exp((double)x);
}

// exact mirror of jax.nn.softmax([l0,l1])[1] in fp32, fast-math-immune
__device__ __forceinline__ float softmax1(float l0, float l1){
    float m = fmaxf(l0, l1);
    float e0 = exp_strict(__fsub_rn(l0, m));
    float e1 = exp_strict(__fsub_rn(l1, m));
    return __fdiv_rn(e1, __fadd_rn(e0, e1));
}

// ---------------- weight permutes ----------------
__global__ void k_transpose(const float* __restrict__ src, int K, int which){
    float* dst = which ? g_rwT : g_bbT;
    int t = blockIdx.x*blockDim.x + threadIdx.x;
    if (t < K*128){
        int i = t >> 7, c = t & 127;
        dst[t] = src[c*K + i];
    }
}

__global__ void __launch_bounds__(256) k_tfc1(const float* __restrict__ w){
    __shared__ float s[FK];
    int h = blockIdx.x;
    const float* src = w + (size_t)h*FK;
    for (int t = threadIdx.x; t < FK; t += 256) s[t] = src[t];
    __syncthreads();
    float* dst = g_fc1wP + (size_t)h*FK;
    for (int t = threadIdx.x; t < FK; t += 256){
        int p = t >> 7, c = t & 127;
        dst[t] = s[c*49 + p];
    }
}

__global__ void k_init(){
    int t = blockIdx.x*blockDim.x + threadIdx.x;
    if (t < NPAD1 - NANCH){ g_key1[NANCH+t] = -1.f; g_idx1[NANCH+t] = 0x7fffffff; }
    if (t < NPAD2 - KP)   { g_key2[KP+t]    = -1.f; g_idx2[KP+t]    = 0x7fffffff; }
}

// ---------------- conv1: 3->128, 16x16 stride16 VALID, relu (fp64 accum — REQUIRED) ----------------
__global__ void __launch_bounds__(128) k_conv1(const float* __restrict__ x, const float* __restrict__ bias){
    __shared__ float sp[4*768];
    int gy  = blockIdx.x >> 3;
    int gx0 = (blockIdx.x & 7) * 4;
    int tid = threadIdx.x;
    for (int e = tid; e < 3072; e += 128){
        int spx = e / 768, i = e % 768;
        int ci = i >> 8, rr = i & 255, ky = rr >> 4, kx = rr & 15;
        sp[e] = x[ci*(512*512) + (gy*16+ky)*512 + (gx0+spx)*16 + kx];
    }
    __syncthreads();
    double a0=0, a1=0, a2=0, a3=0;
    for (int i = 0; i < 768; i++){
        double w = (double)g_bbT[i*128 + tid];
        a0 = fma((double)sp[i],      w, a0);
        a1 = fma((double)sp[768+i],  w, a1);
        a2 = fma((double)sp[1536+i], w, a2);
        a3 = fma((double)sp[2304+i], w, a3);
    }
    float b = bias[tid];
    int base = (gy*32 + gx0)*128 + tid;
    g_featT[base      ] = fmaxf(__fadd_rn((float)a0, b), 0.f);
    g_featT[base + 128] = fmaxf(__fadd_rn((float)a1, b), 0.f);
    g_featT[base + 256] = fmaxf(__fadd_rn((float)a2, b), 0.f);
    g_featT[base + 384] = fmaxf(__fadd_rn((float)a3, b), 0.f);
}

// ---------------- conv2: 3x3 SAME 128->128, relu (fp64 accum — REQUIRED) ----------------
__global__ void __launch_bounds__(128) k_conv2(const float* __restrict__ bias){
    __shared__ float sp[18*128];
    int gy  = blockIdx.x >> 3;
    int gx0 = (blockIdx.x & 7) * 4;
    int tid = threadIdx.x;
    for (int e = tid; e < 18*128; e += 128){
        int pix = e >> 7, ci = e & 127;
        int ky = pix / 6, sx = pix % 6;
        int iy = gy + ky - 1, ix = gx0 + sx - 1;
        float v = 0.f;
        if (iy >= 0 && iy < 32 && ix >= 0 && ix < 32) v = g_featT[(iy*32+ix)*128 + ci];
        sp[e] = v;
    }
    __syncthreads();
    double a0=0, a1=0, a2=0, a3=0;
    int i = 0;
    for (int ci = 0; ci < 128; ci++){
        #pragma unroll
        for (int ky = 0; ky < 3; ky++){
            #pragma unroll
            for (int kx = 0; kx < 3; kx++){
                double w = (double)g_rwT[i*128 + tid];
                int base = (ky*6+kx)*128 + ci;
                a0 = fma((double)sp[base      ], w, a0);
                a1 = fma((double)sp[base + 128], w, a1);
                a2 = fma((double)sp[base + 256], w, a2);
                a3 = fma((double)sp[base + 384], w, a3);
                i++;
            }
        }
    }
    float b = bias[tid];
    int ob = (gy*32+gx0)*128 + tid;
    g_hT[ob      ] = fmaxf(__fadd_rn((float)a0, b), 0.f);
    g_hT[ob + 128] = fmaxf(__fadd_rn((float)a1, b), 0.f);
    g_hT[ob + 256] = fmaxf(__fadd_rn((float)a2, b), 0.f);
    g_hT[ob + 384] = fmaxf(__fadd_rn((float)a3, b), 0.f);
}

// ---------------- RPN heads + softmax + anchors + decode + clip (fp64 dots — REQUIRED) ----------------
__global__ void __launch_bounds__(64) k_rpn(const float* __restrict__ cw, const float* __restrict__ cb,
                                            const float* __restrict__ rw, const float* __restrict__ rb,
                                            float* __restrict__ out){
    __shared__ float sh[128];
    __shared__ float sd[54];
    int pix = blockIdx.x;
    int tid = threadIdx.x;
    sh[tid]      = g_hT[pix*128 + tid];
    sh[tid + 64] = g_hT[pix*128 + tid + 64];
    __syncthreads();
    if (tid < 54){
        const float* wrow = (tid < 18) ? (cw + tid*128) : (rw + (tid-18)*128);
        float bb = (tid < 18) ? cb[tid] : rb[tid-18];
        double acc = 0.0;
        for (int c = 0; c < 128; c++) acc = fma((double)sh[c], (double)wrow[c], acc);
        sd[tid] = __fadd_rn((float)acc, bb);
    }
    __syncthreads();
    if (tid < 9){
        int a = tid;
        int y = pix >> 5, x = pix & 31;
        int n = pix*9 + a;
        float l0 = sd[2*a], l1 = sd[2*a+1];
        out[O_RPNL + n*2+0] = l0; out[O_RPNL + n*2+1] = l1;
        float d0 = sd[18+4*a+0], d1 = sd[18+4*a+1], d2 = sd[18+4*a+2], d3 = sd[18+4*a+3];
        out[O_RPND + n*4+0]=d0; out[O_RPND + n*4+1]=d1;
        out[O_RPND + n*4+2]=d2; out[O_RPND + n*4+3]=d3;
        const float scv[3] = {32.f, 64.f, 128.f};
        const float rv[3]  = {0.5f, 1.f, 2.f};
        int si = a/3, ri = a%3;
        float sr = __fsqrt_rn(rv[ri]);
        float ws = __fdiv_rn(scv[si], sr);
        float hs = __fmul_rn(scv[si], sr);
        float cx = __fmul_rn(__fadd_rn((float)x, 0.5f), 16.f);
        float cy = __fmul_rn(__fadd_rn((float)y, 0.5f), 16.f);
        float W2 = __fmul_rn(ws, 0.5f);
        float H2 = __fmul_rn(hs, 0.5f);
        float ax1 = __fsub_rn(cx, W2), ay1 = __fsub_rn(cy, H2);
        float ax2 = __fadd_rn(cx, W2), ay2 = __fadd_rn(cy, H2);
        out[O_ANCH + n*4+0]=ax1; out[O_ANCH + n*4+1]=ay1;
        out[O_ANCH + n*4+2]=ax2; out[O_ANCH + n*4+3]=ay2;
        float w = __fadd_rn(__fsub_rn(ax2, ax1), 1.f);
        float h = __fadd_rn(__fsub_rn(ay2, ay1), 1.f);
        float ccx = __fadd_rn(ax1, __fmul_rn(0.5f, w));
        float ccy = __fadd_rn(ay1, __fmul_rn(0.5f, h));
        float pcx = __fadd_rn(__fmul_rn(d0, w), ccx);
        float pcy = __fadd_rn(__fmul_rn(d1, h), ccy);
        float pw = __fmul_rn(exp_strict(d2), w);
        float ph = __fmul_rn(exp_strict(d3), h);
        float hw = __fmul_rn(0.5f, pw), hh = __fmul_rn(0.5f, ph);
        g_boxes[n*4+0] = fminf(fmaxf(__fsub_rn(pcx, hw), 0.f), 511.f);
        g_boxes[n*4+1] = fminf(fmaxf(__fsub_rn(pcy, hh), 0.f), 511.f);
        g_boxes[n*4+2] = fminf(fmaxf(__fadd_rn(pcx, hw), 0.f), 511.f);
        g_boxes[n*4+3] = fminf(fmaxf(__fadd_rn(pcy, hh), 0.f), 511.f);
        g_key1[n] = softmax1(l0, l1);
        g_idx1[n] = n;
    }
}

// ---------------- hybrid bitonic sort (desc score, tie idx asc) ----------------
__device__ __forceinline__ bool cmp_before(float ka, int ia, float kb, int ib){
    return (ka > kb) || (ka == kb && ia < ib);
}

__global__ void __launch_bounds__(1024) k_sort_local(float* __restrict__ key, int* __restrict__ idx){
    __shared__ float sk[2048];
    __shared__ int   si[2048];
    int base = blockIdx.x * 2048;
    for (int t = threadIdx.x; t < 2048; t += 1024){ sk[t] = key[base+t]; si[t] = idx[base+t]; }
    __syncthreads();
    for (int kk = 2; kk <= 2048; kk <<= 1){
        for (int j = kk >> 1; j > 0; j >>= 1){
            for (int t = threadIdx.x; t < 2048; t += 1024){
                int p = t ^ j;
                if (p > t){
                    bool up = (((base + t) & kk) == 0);
                    float ka = sk[t], kb = sk[p];
                    int ia = si[t], ib = si[p];
                    bool sw = up ? cmp_before(kb, ib, ka, ia) : cmp_before(ka, ia, kb, ib);
                    if (sw){ sk[t]=kb; si[t]=ib; sk[p]=ka; si[p]=ia; }
                }
            }
            __syncthreads();
        }
    }
    for (int t = threadIdx.x; t < 2048; t += 1024){ key[base+t] = sk[t]; idx[base+t] = si[t]; }
}

__global__ void __launch_bounds__(256) k_sort_global(float* __restrict__ key, int* __restrict__ idx,
                                                     int kk, int j, int npad){
    int i = blockIdx.x*256 + threadIdx.x;
    int p = i ^ j;
    if (i < npad && p > i && p < npad){
        bool up = ((i & kk) == 0);
        float ka = key[i], kb = key[p];
        int ia = idx[i], ib = idx[p];
        bool sw = up ? cmp_before(kb, ib, ka, ia) : cmp_before(ka, ia, kb, ib);
        if (sw){ key[i]=kb; idx[i]=ib; key[p]=ka; idx[p]=ia; }
    }
}

__global__ void __launch_bounds__(1024) k_merge_local(float* __restrict__ key, int* __restrict__ idx, int kk){
    __shared__ float sk[2048];
    __shared__ int   si[2048];
    int base = blockIdx.x * 2048;
    for (int t = threadIdx.x; t < 2048; t += 1024){ sk[t] = key[base+t]; si[t] = idx[base+t]; }
    __syncthreads();
    for (int j = 1024; j > 0; j >>= 1){
        for (int t = threadIdx.x; t < 2048; t += 1024){
            int p = t ^ j;
            if (p > t){
                bool up = (((base + t) & kk) == 0);
                float ka = sk[t], kb = sk[p];
                int ia = si[t], ib = si[p];
                bool sw = up ? cmp_before(kb, ib, ka, ia) : cmp_before(ka, ia, kb, ib);
                if (sw){ sk[t]=kb; si[t]=ib; sk[p]=ka; si[p]=ia; }
            }
        }
        __syncthreads();
    }
    for (int t = threadIdx.x; t < 2048; t += 1024){ key[base+t] = sk[t]; idx[base+t] = si[t]; }
}

// ---------------- gathers ----------------
__global__ void k_gather1(){
    int i = blockIdx.x*blockDim.x + threadIdx.x;
    if (i < NANCH){
        int id = g_idx1[i];
        ((float4*)g_sbox1)[i] = ((const float4*)g_boxes)[id];
    }
}

__global__ void k_gather2(){
    int i = blockIdx.x*blockDim.x + threadIdx.x;
    if (i < KP){
        int id = g_idx2[i];
        ((float4*)g_sdet)[i] = ((const float4*)g_dets)[id];
    }
}

// ---------------- NMS mask build (round-10 body + triangle skip + div skip) ----------------
// Lower-triangle blocks return immediately: their mask words are never read by
// the scan (at group g only word g of earlier rows is consumed).
__global__ void __launch_bounds__(64) k_mask(const float* __restrict__ sbox, int n, int nbw,
                                             unsigned long long* __restrict__ mask, float thr){
    int ib = blockIdx.y, jb = blockIdx.x;
    if (jb < ib) return;
    __shared__ float4 cb[64];
    __shared__ float  ca[64];
    int cj = jb*64 + threadIdx.x;
    if (cj < n){
        float4 b = ((const float4*)sbox)[cj];
        cb[threadIdx.x] = b;
        ca[threadIdx.x] = __fmul_rn(__fadd_rn(__fsub_rn(b.z,b.x),1.f), __fadd_rn(__fsub_rn(b.w,b.y),1.f));
    } else {
        cb[threadIdx.x] = make_float4(0,0,0,0);
        ca[threadIdx.x] = 1.f;
    }
    __syncthreads();
    int r = ib*64 + threadIdx.x;
    if (r >= n) return;
    float4 rb = ((const float4*)sbox)[r];
    float ra = __fmul_rn(__fadd_rn(__fsub_rn(rb.z,rb.x),1.f), __fadd_rn(__fsub_rn(rb.w,rb.y),1.f));
    unsigned long long m = 0;
    if (jb*64 + 63 > r){
        #pragma unroll 4
        for (int b = 0; b < 64; b++){
            int j = jb*64 + b;
            if (j > r && j < n){
                float4 o = cb[b];
                float xx1 = fmaxf(rb.x, o.x), yy1 = fmaxf(rb.y, o.y);
                float xx2 = fminf(rb.z, o.z), yy2 = fminf(rb.w, o.w);
                float iw = fmaxf(__fadd_rn(__fsub_rn(xx2,xx1),1.f), 0.f);
                float ih = fmaxf(__fadd_rn(__fsub_rn(yy2,yy1),1.f), 0.f);
                float inter = __fmul_rn(iw, ih);
                if (inter > 0.f){
                    float iou = __fdiv_rn(inter, __fsub_rn(__fadd_rn(ra, ca[b]), inter));
                    if (iou > thr) m |= (1ULL << b);
                }
            }
        }
    }
    mask[(size_t)r*nbw + jb] = m;
}

// ---------------- NMS scans (round-10: single warp, 4-deep prefetch) ----------------
__device__ __forceinline__ void nms_load1(int i, unsigned long long (&buf)[5], int lane){
    #pragma unroll
    for (int q = 0; q < 5; q++){
        int wq = q*32 + lane;
        buf[q] = (i < NANCH && wq < NBW1) ? g_mask1[(size_t)i*NBW1 + wq] : 0ULL;
    }
}
__device__ __forceinline__ bool nms_step1(int i, unsigned long long (&buf)[5],
                                          unsigned long long (&remv)[5], int lane, int &cnt){
    int w = i >> 6, slot = w >> 5, owner = w & 31;
    unsigned long long myw = slot==0?remv[0]:slot==1?remv[1]:slot==2?remv[2]:slot==3?remv[3]:remv[4];
    unsigned long long cur = __shfl_sync(0xffffffffu, myw, owner);
    if (!((cur >> (i & 63)) & 1ULL)){
        if (lane == 0 && cnt < KP) g_keep1[cnt] = g_idx1[i];
        cnt++;
        if (cnt >= KP) return true;
        #pragma unroll
        for (int q = 0; q < 5; q++) remv[q] |= buf[q];
    }
    return false;
}
__global__ void k_scan1(){
    int lane = threadIdx.x;
    unsigned long long remv[5] = {0,0,0,0,0};
    unsigned long long b0[5], b1[5], b2[5], b3[5];
    int cnt = 0;
    nms_load1(0,b0,lane); nms_load1(1,b1,lane); nms_load1(2,b2,lane); nms_load1(3,b3,lane);
    for (int i = 0; i < NANCH; i += 4){
        if (nms_step1(i+0, b0, remv, lane, cnt)) break;
        nms_load1(i+4, b0, lane);
        if (nms_step1(i+1, b1, remv, lane, cnt)) break;
        nms_load1(i+5, b1, lane);
        if (nms_step1(i+2, b2, remv, lane, cnt)) break;
        nms_load1(i+6, b2, lane);
        if (nms_step1(i+3, b3, remv, lane, cnt)) break;
        nms_load1(i+7, b3, lane);
    }
    for (int t = cnt + lane; t < KP; t += 32) g_keep1[t] = 0;
}

__device__ __forceinline__ bool nms_step2(int i, unsigned long long buf,
                                          unsigned long long &remv, int lane, int &cnt){
    int w = i >> 6;
    unsigned long long cur = __shfl_sync(0xffffffffu, remv, w);
    if (!((cur >> (i & 63)) & 1ULL)){
        if (lane == 0 && cnt < KP) g_keep2[cnt] = g_idx2[i];
        cnt++;
        if (cnt >= KP) return true;
        remv |= buf;
    }
    return false;
}
__global__ void k_scan2(){
    int lane = threadIdx.x;
    unsigned long long remv = 0;
    unsigned long long b0, b1, b2, b3;
    int cnt = 0;
    b0 = g_mask2[(size_t)0*NBW2 + lane];
    b1 = g_mask2[(size_t)1*NBW2 + lane];
    b2 = g_mask2[(size_t)2*NBW2 + lane];
    b3 = g_mask2[(size_t)3*NBW2 + lane];
    for (int i = 0; i < KP; i += 4){
        if (nms_step2(i+0, b0, remv, lane, cnt)) break;
        b0 = (i+4 < KP) ? g_mask2[(size_t)(i+4)*NBW2 + lane] : 0ULL;
        if (nms_step2(i+1, b1, remv, lane, cnt)) break;
        b1 = (i+5 < KP) ? g_mask2[(size_t)(i+5)*NBW2 + lane] : 0ULL;
        if (nms_step2(i+2, b2, remv, lane, cnt)) break;
        b2 = (i+6 < KP) ? g_mask2[(size_t)(i+6)*NBW2 + lane] : 0ULL;
        if (nms_step2(i+3, b3, remv, lane, cnt)) break;
        b3 = (i+7 < KP) ? g_mask2[(size_t)(i+7)*NBW2 + lane] : 0ULL;
    }
    if (lane == 0) g_nk2 = cnt;
    for (int t = cnt + lane; t < KP; t += 32) g_keep2[t] = 0;
}

// ---------------- proposals ----------------
__global__ void k_props(float* __restrict__ out){
    int i = blockIdx.x*blockDim.x + threadIdx.x;
    if (i < KP){
        int id = g_keep1[i];
        float4 b = ((const float4*)g_boxes)[id];
        out[O_PROPS + i*4+0] = b.x; out[O_PROPS + i*4+1] = b.y;
        out[O_PROPS + i*4+2] = b.z; out[O_PROPS + i*4+3] = b.w;
        ((float4*)g_prop4)[i] = b;
        g_nbox[i*4+0] = __fdiv_rn(b.y, 511.f);
        g_nbox[i*4+1] = __fdiv_rn(b.x, 511.f);
        g_nbox[i*4+2] = __fdiv_rn(b.w, 511.f);
        g_nbox[i*4+3] = __fdiv_rn(b.z, 511.f);
    }
}

// ---------------- crop + bilinear + 2x2 maxpool ----------------
__global__ void __launch_bounds__(256) k_crop(){
    int k = blockIdx.x;
    int warp = threadIdx.x >> 5, lane = threadIdx.x & 31;
    float y1 = g_nbox[k*4+0], x1 = g_nbox[k*4+1], y2 = g_nbox[k*4+2], x2 = g_nbox[k*4+3];
    float dy = __fsub_rn(y2, y1), dx = __fsub_rn(x2, x1);
    int c4 = lane*4;
    const float4* f = (const float4*)g_featT;
    for (int p = warp; p < 49; p += 8){
        int oi = p/7, oj = p%7;
        float4 acc = make_float4(-1e30f,-1e30f,-1e30f,-1e30f);
        #pragma unroll
        for (int di = 0; di < 2; di++){
            #pragma unroll
            for (int dj = 0; dj < 2; dj++){
                int ti = 2*oi+di, tj = 2*oj+dj;
                float ty = __fdiv_rn((float)ti, 13.f);
                float tx = __fdiv_rn((float)tj, 13.f);
                float ys = __fmul_rn(__fadd_rn(y1, __fmul_rn(ty, dy)), 31.f);
                float xs = __fmul_rn(__fadd_rn(x1, __fmul_rn(tx, dx)), 31.f);
                int y0 = min(max((int)floorf(ys), 0), 31);
                int y1i = min(y0+1, 31);
                int x0 = min(max((int)floorf(xs), 0), 31);
                int x1i = min(x0+1, 31);
                float wy = __fsub_rn(ys, (float)y0);
                float wx = __fsub_rn(xs, (float)x0);
                float omwx = __fsub_rn(1.f, wx), omwy = __fsub_rn(1.f, wy);
                float4 f00 = f[((y0*32+x0)*128 + c4) >> 2];
                float4 f01 = f[((y0*32+x1i)*128 + c4) >> 2];
                float4 f10 = f[((y1i*32+x0)*128 + c4) >> 2];
                float4 f11 = f[((y1i*32+x1i)*128 + c4) >> 2];
                #pragma unroll
                for (int e = 0; e < 4; e++){
                    float a00 = (&f00.x)[e], a01 = (&f01.x)[e];
                    float a10 = (&f10.x)[e], a11 = (&f11.x)[e];
                    float top = __fadd_rn(__fmul_rn(a00, omwx), __fmul_rn(a01, wx));
                    float bot = __fadd_rn(__fmul_rn(a10, omwx), __fmul_rn(a11, wx));
                    float val = __fadd_rn(__fmul_rn(top, omwy), __fmul_rn(bot, wy));
                    (&acc.x)[e] = fmaxf((&acc.x)[e], val);
                }
            }
        }
        ((float4*)g_flat)[((size_t)k*FK + p*128 + c4) >> 2] = acc;
    }
}

// ---------------- fp32 SIMT GEMM (round-10): 128x128 tile, 8x8 micro, double-buffered ----------------
#define GP 132
__global__ void __launch_bounds__(256) k_gemm(const float* __restrict__ A, const float* __restrict__ B,
                                              const float* __restrict__ bias, float* __restrict__ Cmat,
                                              int M, int N, int K){
    __shared__ float As[2][16][GP];
    __shared__ float Bs[2][16][GP];
    int tid = threadIdx.x;
    int tx = tid & 15, ty = tid >> 4;
    int mbase = blockIdx.y*128, nbase = blockIdx.x*128;
    float acc[8][8];
    #pragma unroll
    for (int r = 0; r < 8; r++)
        #pragma unroll
        for (int q = 0; q < 8; q++) acc[r][q] = 0.f;

    int r0 = tid >> 2,          c0 = (tid & 3) * 4;
    int r1 = (tid + 256) >> 2,  c1 = ((tid + 256) & 3) * 4;
    const float* Ap0 = A + (size_t)(mbase + r0)*K + c0;
    const float* Ap1 = A + (size_t)(mbase + r1)*K + c1;
    const float* Bp0 = B + (size_t)(nbase + r0)*K + c0;
    const float* Bp1 = B + (size_t)(nbase + r1)*K + c1;
    bool av0 = (mbase + r0) < M, av1 = (mbase + r1) < M;

    float4 a0 = av0 ? *(const float4*)Ap0 : make_float4(0,0,0,0);
    float4 a1 = av1 ? *(const float4*)Ap1 : make_float4(0,0,0,0);
    float4 b0 = *(const float4*)Bp0;
    float4 b1 = *(const float4*)Bp1;
    As[0][c0+0][r0]=a0.x; As[0][c0+1][r0]=a0.y; As[0][c0+2][r0]=a0.z; As[0][c0+3][r0]=a0.w;
    As[0][c1+0][r1]=a1.x; As[0][c1+1][r1]=a1.y; As[0][c1+2][r1]=a1.z; As[0][c1+3][r1]=a1.w;
    Bs[0][c0+0][r0]=b0.x; Bs[0][c0+1][r0]=b0.y; Bs[0][c0+2][r0]=b0.z; Bs[0][c0+3][r0]=b0.w;
    Bs[0][c1+0][r1]=b1.x; Bs[0][c1+1][r1]=b1.y; Bs[0][c1+2][r1]=b1.z; Bs[0][c1+3][r1]=b1.w;
    __syncthreads();

    int nIter = K / 16;
    for (int it = 0; it < nIter; it++){
        int buf = it & 1;
        float4 na0, na1, nb0, nb1;
        if (it + 1 < nIter){
            int koff = (it+1)*16;
            na0 = av0 ? *(const float4*)(Ap0 + koff) : make_float4(0,0,0,0);
            na1 = av1 ? *(const float4*)(Ap1 + koff) : make_float4(0,0,0,0);
            nb0 = *(const float4*)(Bp0 + koff);
            nb1 = *(const float4*)(Bp1 + koff);
        }
        #pragma unroll
        for (int kk = 0; kk < 16; kk++){
            float ar[8], br[8];
            *(float4*)(ar)   = *(const float4*)&As[buf][kk][ty*8];
            *(float4*)(ar+4) = *(const float4*)&As[buf][kk][ty*8+4];
            *(float4*)(br)   = *(const float4*)&Bs[buf][kk][tx*8];
            *(float4*)(br+4) = *(const float4*)&Bs[buf][kk][tx*8+4];
            #pragma unroll
            for (int r = 0; r < 8; r++)
                #pragma unroll
                for (int q = 0; q < 8; q++)
                    acc[r][q] = fmaf(ar[r], br[q], acc[r][q]);
        }
        if (it + 1 < nIter){
            int nb = buf ^ 1;
            __syncthreads();
            As[nb][c0+0][r0]=na0.x; As[nb][c0+1][r0]=na0.y; As[nb][c0+2][r0]=na0.z; As[nb][c0+3][r0]=na0.w;
            As[nb][c1+0][r1]=na1.x; As[nb][c1+1][r1]=na1.y; As[nb][c1+2][r1]=na1.z; As[nb][c1+3][r1]=na1.w;
            Bs[nb][c0+0][r0]=nb0.x; Bs[nb][c0+1][r0]=nb0.y; Bs[nb][c0+2][r0]=nb0.z; Bs[nb][c0+3][r0]=nb0.w;
            Bs[nb][c1+0][r1]=nb1.x; Bs[nb][c1+1][r1]=nb1.y; Bs[nb][c1+2][r1]=nb1.z; Bs[nb][c1+3][r1]=nb1.w;
            __syncthreads();
        }
    }
    #pragma unroll
    for (int r = 0; r < 8; r++){
        int row = mbase + ty*8 + r;
        if (row < M){
            #pragma unroll
            for (int q = 0; q < 8; q++){
                int col = nbase + tx*8 + q;
                Cmat[(size_t)row*N + col] = fmaxf(__fadd_rn(acc[r][q], bias[col]), 0.f);
            }
        }
    }
}

// ---------------- RCNN heads + decode2 (fp64 dots — decision path) ----------------
__global__ void __launch_bounds__(192) k_heads(const float* __restrict__ cw, const float* __restrict__ cb,
                                               const float* __restrict__ rw, const float* __restrict__ rb,
                                               float* __restrict__ out){
    __shared__ float sd[6];
    int k = blockIdx.x;
    int warp = threadIdx.x >> 5, lane = threadIdx.x & 31;
    const float4* h4 = (const float4*)(g_h2 + (size_t)k*1024);
    const float4* w4 = (const float4*)((warp < 2) ? (cw + warp*1024) : (rw + (warp-2)*1024));
    double acc = 0.0;
    #pragma unroll
    for (int q = 0; q < 8; q++){
        float4 a = h4[lane + q*32], b = w4[lane + q*32];
        acc = fma((double)a.x, (double)b.x, acc);
        acc = fma((double)a.y, (double)b.y, acc);
        acc = fma((double)a.z, (double)b.z, acc);
        acc = fma((double)a.w, (double)b.w, acc);
    }
    #pragma unroll
    for (int o = 16; o; o >>= 1) acc += __shfl_xor_sync(0xffffffffu, acc, o);
    if (lane == 0) sd[warp] = __fadd_rn((float)acc, (warp < 2) ? cb[warp] : rb[warp-2]);
    __syncthreads();
    if (threadIdx.x == 0){
        float l0 = sd[0], l1 = sd[1];
        out[O_RCL + k*2+0] = l0; out[O_RCL + k*2+1] = l1;
        float d0 = sd[2], d1 = sd[3], d2 = sd[4], d3 = sd[5];
        out[O_RCD + k*4+0]=d0; out[O_RCD + k*4+1]=d1;
        out[O_RCD + k*4+2]=d2; out[O_RCD + k*4+3]=d3;
        float score = softmax1(l0, l1);
        float4 pr = ((const float4*)g_prop4)[k];
        float w = __fadd_rn(__fsub_rn(pr.z, pr.x), 1.f);
        float h = __fadd_rn(__fsub_rn(pr.w, pr.y), 1.f);
        float ccx = __fadd_rn(pr.x, __fmul_rn(0.5f, w));
        float ccy = __fadd_rn(pr.y, __fmul_rn(0.5f, h));
        float pcx = __fadd_rn(__fmul_rn(d0, w), ccx);
        float pcy = __fadd_rn(__fmul_rn(d1, h), ccy);
        float pw = __fmul_rn(exp_strict(d2), w);
        float ph = __fmul_rn(exp_strict(d3), h);
        float hw = __fmul_rn(0.5f, pw), hh = __fmul_rn(0.5f, ph);
        float4 dt;
        dt.x = fminf(fmaxf(__fsub_rn(pcx, hw), 0.f), 511.f);
        dt.y = fminf(fmaxf(__fsub_rn(pcy, hh), 0.f), 511.f);
        dt.z = fminf(fmaxf(__fadd_rn(pcx, hw), 0.f), 511.f);
        dt.w = fminf(fmaxf(__fadd_rn(pcy, hh), 0.f), 511.f);
        ((float4*)g_dets)[k] = dt;
        g_rsc[k] = score;
        g_key2[k] = score;
        g_idx2[k] = k;
    }
}

// ---------------- final outputs ----------------
__global__ void k_final(float* __restrict__ out){
    int i = blockIdx.x*blockDim.x + threadIdx.x;
    if (i < KP){
        float m = (i < g_nk2) ? 1.f : 0.f;
        int id = g_keep2[i];
        float4 d = ((const float4*)g_dets)[id];
        out[O_DETS + i*4+0] = d.x*m; out[O_DETS + i*4+1] = d.y*m;
        out[O_DETS + i*4+2] = d.z*m; out[O_DETS + i*4+3] = d.w*m;
        out[O_SC + i] = g_rsc[id]*m;
    }
}

// ---------------- launch ----------------
extern "C" void kernel_launch(void* const* d_in, const int* in_sizes, int n_in,
                              void* d_out, int out_size){
    const float* x        = (const float*)d_in[0];
    const float* bb_w     = (const float*)d_in[1];
    const float* bb_b     = (const float*)d_in[2];
    const float* rpn_w    = (const float*)d_in[3];
    const float* rpn_b    = (const float*)d_in[4];
    const float* rpn_cls_w= (const float*)d_in[5];
    const float* rpn_cls_b= (const float*)d_in[6];
    const float* rpn_reg_w= (const float*)d_in[7];
    const float* rpn_reg_b= (const float*)d_in[8];
    const float* fc1_w    = (const float*)d_in[9];
    const float* fc1_b    = (const float*)d_in[10];
    const float* fc2_w    = (const float*)d_in[11];
    const float* fc2_b    = (const float*)d_in[12];
    const float* cls_w    = (const float*)d_in[13];
    const float* cls_b    = (const float*)d_in[14];
    const float* reg_w    = (const float*)d_in[15];
    const float* reg_b    = (const float*)d_in[16];
    float* out = (float*)d_out;

    float *p_key1, *p_key2, *p_sbox1, *p_sdet, *p_flat, *p_fc1wP, *p_h1, *p_h2;
    int *p_idx1, *p_idx2;
    unsigned long long *p_mask1, *p_mask2;
    cudaGetSymbolAddress((void**)&p_key1,  g_key1);
    cudaGetSymbolAddress((void**)&p_idx1,  g_idx1);
    cudaGetSymbolAddress((void**)&p_key2,  g_key2);
    cudaGetSymbolAddress((void**)&p_idx2,  g_idx2);
    cudaGetSymbolAddress((void**)&p_sbox1, g_sbox1);
    cudaGetSymbolAddress((void**)&p_sdet,  g_sdet);
    cudaGetSymbolAddress((void**)&p_mask1, g_mask1);
    cudaGetSymbolAddress((void**)&p_mask2, g_mask2);
    cudaGetSymbolAddress((void**)&p_flat,  g_flat);
    cudaGetSymbolAddress((void**)&p_fc1wP, g_fc1wP);
    cudaGetSymbolAddress((void**)&p_h1,    g_h1);
    cudaGetSymbolAddress((void**)&p_h2,    g_h2);

    k_transpose<<<(768*128+255)/256, 256>>>(bb_w, 768, 0);
    k_transpose<<<(1152*128+255)/256, 256>>>(rpn_w, 1152, 1);
    k_tfc1<<<1024, 256>>>(fc1_w);
    k_init<<<32, 256>>>();

    k_conv1<<<256, 128>>>(x, bb_b);
    k_conv2<<<256, 128>>>(rpn_b);
    k_rpn<<<1024, 64>>>(rpn_cls_w, rpn_cls_b, rpn_reg_w, rpn_reg_b, out);

    // hybrid bitonic sort over 16384 (desc score, tie idx asc)
    k_sort_local<<<8, 1024>>>(p_key1, p_idx1);
    for (int kk = 4096; kk <= NPAD1; kk <<= 1){
        for (int j = kk >> 1; j >= 2048; j >>= 1)
            k_sort_global<<<NPAD1/256, 256>>>(p_key1, p_idx1, kk, j, NPAD1);
        k_merge_local<<<8, 1024>>>(p_key1, p_idx1, kk);
    }

    k_gather1<<<(NANCH+255)/256, 256>>>();
    {
        dim3 g(NBW1, NBW1);
        k_mask<<<g, 64>>>(p_sbox1, NANCH, NBW1, p_mask1, 0.5f);
    }
    k_scan1<<<1, 32>>>();
    k_props<<<(KP+255)/256, 256>>>(out);
    k_crop<<<KP, 256>>>();

    {
        dim3 g1(8, 16);
        k_gemm<<<g1, 256>>>(p_flat, p_fc1wP, fc1_b, p_h1, KP, 1024, FK);
        k_gemm<<<g1, 256>>>(p_h1, fc2_w, fc2_b, p_h2, KP, 1024, 1024);
    }
    k_heads<<<KP, 192>>>(cls_w, cls_b, reg_w, reg_b, out);

    k_sort_local<<<1, 1024>>>(p_key2, p_idx2);

    k_gather2<<<(KP+255)/256, 256>>>();
    {
        dim3 g(NBW2, NBW2);
        k_mask<<<g, 64>>>(p_sdet, KP, NBW2, p_mask2, 0.3f);
    }
    k_scan2<<<1, 32>>>();
    k_final<<<(KP+255)/256, 256>>>(out);
}

// round 13
// speedup vs baseline: 1.8674x; 1.2649x over previous
#include <cuda_runtime.h>
#include <math.h>

#define NANCH 9216
#define NPAD1 16384
#define NBW1  144
#define KP    2000
#define NPAD2 2048
#define NBW2  32
#define FK    6272

// output offsets (floats)
#define O_RPNL  0
#define O_RPND  18432
#define O_PROPS 55296
#define O_ANCH  63296
#define O_RCL   100160
#define O_RCD   104160
#define O_DETS  112160
#define O_SC    120160

// ---------------- device scratch ----------------
__device__ __align__(16) float g_featT[32*32*128];
__device__ __align__(16) float g_hT[32*32*128];
__device__ __align__(16) float g_bbT[768*128];
__device__ __align__(16) float g_rwT[1152*128];
__device__ __align__(16) float g_fc1wP[1024*FK];
__device__ __align__(16) float g_boxes[NANCH*4];
__device__ float g_key1[NPAD1];
__device__ int   g_idx1[NPAD1];
__device__ __align__(16) float g_sbox1[NANCH*4];
__device__ unsigned long long g_mask1[(size_t)NANCH*NBW1];
__device__ int   g_keep1[KP];
__device__ __align__(16) float g_prop4[KP*4];
__device__ __align__(16) float g_nbox[KP*4];
__device__ __align__(16) float g_flat[(size_t)KP*FK];
__device__ __align__(16) float g_h1[KP*1024];
__device__ __align__(16) float g_h2[KP*1024];
__device__ float g_rsc[KP];
__device__ __align__(16) float g_dets[KP*4];
__device__ float g_key2[NPAD2];
__device__ int   g_idx2[NPAD2];
__device__ __align__(16) float g_sdet[KP*4];
__device__ unsigned long long g_mask2[(size_t)KP*NBW2];
__device__ int   g_keep2[KP];
__device__ int   g_nk2;

// fast-math-immune, correctly-rounded fp32 exp (double exp is never remapped)
__device__ __forceinline__ float exp_strict(float x){
    return (float)exp((double)x);
}

// exact mirror of jax.nn.softmax([l0,l1])[1] in fp32, fast-math-immune
__device__ __forceinline__ float softmax1(float l0, float l1){
    float m = fmaxf(l0, l1);
    float e0 = exp_strict(__fsub_rn(l0, m));
    float e1 = exp_strict(__fsub_rn(l1, m));
    return __fdiv_rn(e1, __fadd_rn(e0, e1));
}

// Compensated (double-float) accumulate: s+c += a*w with ~1e-9 relative error.
// EFT product (exact via fma) + full 2Sum. All ops are _rn intrinsics ->
// immune to fast-math reassociation/contraction.
#define DF_ACC(a, w, s, c) { \
    float _p = __fmul_rn((a), (w)); \
    float _e = __fmaf_rn((a), (w), -_p); \
    float _t = __fadd_rn((s), _p); \
    float _z = __fsub_rn(_t, (s)); \
    float _e2 = __fadd_rn(__fsub_rn(_p, _z), __fsub_rn((s), __fsub_rn(_t, _z))); \
    (s) = _t; \
    (c) = __fadd_rn((c), __fadd_rn(_e, _e2)); \
}

// ---------------- weight permutes ----------------
__global__ void k_transpose(const float* __restrict__ src, int K, int which){
    float* dst = which ? g_rwT : g_bbT;
    int t = blockIdx.x*blockDim.x + threadIdx.x;
    if (t < K*128){
        int i = t >> 7, c = t & 127;
        dst[t] = src[c*K + i];
    }
}

__global__ void __launch_bounds__(256) k_tfc1(const float* __restrict__ w){
    __shared__ float s[FK];
    int h = blockIdx.x;
    const float* src = w + (size_t)h*FK;
    for (int t = threadIdx.x; t < FK; t += 256) s[t] = src[t];
    __syncthreads();
    float* dst = g_fc1wP + (size_t)h*FK;
    for (int t = threadIdx.x; t < FK; t += 256){
        int p = t >> 7, c = t & 127;
        dst[t] = s[c*49 + p];
    }
}

__global__ void k_init(){
    int t = blockIdx.x*blockDim.x + threadIdx.x;
    if (t < NPAD1 - NANCH){ g_key1[NANCH+t] = -1.f; g_idx1[NANCH+t] = 0x7fffffff; }
    if (t < NPAD2 - KP)   { g_key2[KP+t]    = -1.f; g_idx2[KP+t]    = 0x7fffffff; }
}

// ---------------- conv1: 3->128, 16x16 stride16 VALID, relu (compensated fp32) ----------------
__global__ void __launch_bounds__(128) k_conv1(const float* __restrict__ x, const float* __restrict__ bias){
    __shared__ float sp[4*768];
    int gy  = blockIdx.x >> 3;
    int gx0 = (blockIdx.x & 7) * 4;
    int tid = threadIdx.x;
    for (int e = tid; e < 3072; e += 128){
        int spx = e / 768, i = e % 768;
        int ci = i >> 8, rr = i & 255, ky = rr >> 4, kx = rr & 15;
        sp[e] = x[ci*(512*512) + (gy*16+ky)*512 + (gx0+spx)*16 + kx];
    }
    __syncthreads();
    float s0=0.f,c0=0.f, s1=0.f,c1=0.f, s2=0.f,c2=0.f, s3=0.f,c3=0.f;
    for (int i = 0; i < 768; i++){
        float w = g_bbT[i*128 + tid];
        DF_ACC(sp[i],      w, s0, c0);
        DF_ACC(sp[768+i],  w, s1, c1);
        DF_ACC(sp[1536+i], w, s2, c2);
        DF_ACC(sp[2304+i], w, s3, c3);
    }
    float b = bias[tid];
    int base = (gy*32 + gx0)*128 + tid;
    g_featT[base      ] = fmaxf(__fadd_rn(__fadd_rn(s0, c0), b), 0.f);
    g_featT[base + 128] = fmaxf(__fadd_rn(__fadd_rn(s1, c1), b), 0.f);
    g_featT[base + 256] = fmaxf(__fadd_rn(__fadd_rn(s2, c2), b), 0.f);
    g_featT[base + 384] = fmaxf(__fadd_rn(__fadd_rn(s3, c3), b), 0.f);
}

// ---------------- conv2: 3x3 SAME 128->128, relu (compensated fp32) ----------------
__global__ void __launch_bounds__(128) k_conv2(const float* __restrict__ bias){
    __shared__ float sp[18*128];
    int gy  = blockIdx.x >> 3;
    int gx0 = (blockIdx.x & 7) * 4;
    int tid = threadIdx.x;
    for (int e = tid; e < 18*128; e += 128){
        int pix = e >> 7, ci = e & 127;
        int ky = pix / 6, sx = pix % 6;
        int iy = gy + ky - 1, ix = gx0 + sx - 1;
        float v = 0.f;
        if (iy >= 0 && iy < 32 && ix >= 0 && ix < 32) v = g_featT[(iy*32+ix)*128 + ci];
        sp[e] = v;
    }
    __syncthreads();
    float s0=0.f,c0=0.f, s1=0.f,c1=0.f, s2=0.f,c2=0.f, s3=0.f,c3=0.f;
    int i = 0;
    for (int ci = 0; ci < 128; ci++){
        #pragma unroll
        for (int ky = 0; ky < 3; ky++){
            #pragma unroll
            for (int kx = 0; kx < 3; kx++){
                float w = g_rwT[i*128 + tid];
                int base = (ky*6+kx)*128 + ci;
                DF_ACC(sp[base      ], w, s0, c0);
                DF_ACC(sp[base + 128], w, s1, c1);
                DF_ACC(sp[base + 256], w, s2, c2);
                DF_ACC(sp[base + 384], w, s3, c3);
                i++;
            }
        }
    }
    float b = bias[tid];
    int ob = (gy*32+gx0)*128 + tid;
    g_hT[ob      ] = fmaxf(__fadd_rn(__fadd_rn(s0, c0), b), 0.f);
    g_hT[ob + 128] = fmaxf(__fadd_rn(__fadd_rn(s1, c1), b), 0.f);
    g_hT[ob + 256] = fmaxf(__fadd_rn(__fadd_rn(s2, c2), b), 0.f);
    g_hT[ob + 384] = fmaxf(__fadd_rn(__fadd_rn(s3, c3), b), 0.f);
}

// ---------------- RPN heads + softmax + anchors + decode + clip (compensated fp32 dots) ----------------
__global__ void __launch_bounds__(64) k_rpn(const float* __restrict__ cw, const float* __restrict__ cb,
                                            const float* __restrict__ rw, const float* __restrict__ rb,
                                            float* __restrict__ out){
    __shared__ float sh[128];
    __shared__ float sd[54];
    int pix = blockIdx.x;
    int tid = threadIdx.x;
    sh[tid]      = g_hT[pix*128 + tid];
    sh[tid + 64] = g_hT[pix*128 + tid + 64];
    __syncthreads();
    if (tid < 54){
        const float* wrow = (tid < 18) ? (cw + tid*128) : (rw + (tid-18)*128);
        float bb = (tid < 18) ? cb[tid] : rb[tid-18];
        float s = 0.f, c = 0.f;
        for (int cc = 0; cc < 128; cc++){
            DF_ACC(sh[cc], wrow[cc], s, c);
        }
        sd[tid] = __fadd_rn(__fadd_rn(s, c), bb);
    }
    __syncthreads();
    if (tid < 9){
        int a = tid;
        int y = pix >> 5, x = pix & 31;
        int n = pix*9 + a;
        float l0 = sd[2*a], l1 = sd[2*a+1];
        out[O_RPNL + n*2+0] = l0; out[O_RPNL + n*2+1] = l1;
        float d0 = sd[18+4*a+0], d1 = sd[18+4*a+1], d2 = sd[18+4*a+2], d3 = sd[18+4*a+3];
        out[O_RPND + n*4+0]=d0; out[O_RPND + n*4+1]=d1;
        out[O_RPND + n*4+2]=d2; out[O_RPND + n*4+3]=d3;
        const float scv[3] = {32.f, 64.f, 128.f};
        const float rv[3]  = {0.5f, 1.f, 2.f};
        int si = a/3, ri = a%3;
        float sr = __fsqrt_rn(rv[ri]);
        float ws = __fdiv_rn(scv[si], sr);
        float hs = __fmul_rn(scv[si], sr);
        float cx = __fmul_rn(__fadd_rn((float)x, 0.5f), 16.f);
        float cy = __fmul_rn(__fadd_rn((float)y, 0.5f), 16.f);
        float W2 = __fmul_rn(ws, 0.5f);
        float H2 = __fmul_rn(hs, 0.5f);
        float ax1 = __fsub_rn(cx, W2), ay1 = __fsub_rn(cy, H2);
        float ax2 = __fadd_rn(cx, W2), ay2 = __fadd_rn(cy, H2);
        out[O_ANCH + n*4+0]=ax1; out[O_ANCH + n*4+1]=ay1;
        out[O_ANCH + n*4+2]=ax2; out[O_ANCH + n*4+3]=ay2;
        float w = __fadd_rn(__fsub_rn(ax2, ax1), 1.f);
        float h = __fadd_rn(__fsub_rn(ay2, ay1), 1.f);
        float ccx = __fadd_rn(ax1, __fmul_rn(0.5f, w));
        float ccy = __fadd_rn(ay1, __fmul_rn(0.5f, h));
        float pcx = __fadd_rn(__fmul_rn(d0, w), ccx);
        float pcy = __fadd_rn(__fmul_rn(d1, h), ccy);
        float pw = __fmul_rn(exp_strict(d2), w);
        float ph = __fmul_rn(exp_strict(d3), h);
        float hw = __fmul_rn(0.5f, pw), hh = __fmul_rn(0.5f, ph);
        g_boxes[n*4+0] = fminf(fmaxf(__fsub_rn(pcx, hw), 0.f), 511.f);
        g_boxes[n*4+1] = fminf(fmaxf(__fsub_rn(pcy, hh), 0.f), 511.f);
        g_boxes[n*4+2] = fminf(fmaxf(__fadd_rn(pcx, hw), 0.f), 511.f);
        g_boxes[n*4+3] = fminf(fmaxf(__fadd_rn(pcy, hh), 0.f), 511.f);
        g_key1[n] = softmax1(l0, l1);
        g_idx1[n] = n;
    }
}

// ---------------- hybrid bitonic sort (desc score, tie idx asc) ----------------
__device__ __forceinline__ bool cmp_before(float ka, int ia, float kb, int ib){
    return (ka > kb) || (ka == kb && ia < ib);
}

__global__ void __launch_bounds__(1024) k_sort_local(float* __restrict__ key, int* __restrict__ idx){
    __shared__ float sk[2048];
    __shared__ int   si[2048];
    int base = blockIdx.x * 2048;
    for (int t = threadIdx.x; t < 2048; t += 1024){ sk[t] = key[base+t]; si[t] = idx[base+t]; }
    __syncthreads();
    for (int kk = 2; kk <= 2048; kk <<= 1){
        for (int j = kk >> 1; j > 0; j >>= 1){
            for (int t = threadIdx.x; t < 2048; t += 1024){
                int p = t ^ j;
                if (p > t){
                    bool up = (((base + t) & kk) == 0);
                    float ka = sk[t], kb = sk[p];
                    int ia = si[t], ib = si[p];
                    bool sw = up ? cmp_before(kb, ib, ka, ia) : cmp_before(ka, ia, kb, ib);
                    if (sw){ sk[t]=kb; si[t]=ib; sk[p]=ka; si[p]=ia; }
                }
            }
            __syncthreads();
        }
    }
    for (int t = threadIdx.x; t < 2048; t += 1024){ key[base+t] = sk[t]; idx[base+t] = si[t]; }
}

__global__ void __launch_bounds__(256) k_sort_global(float* __restrict__ key, int* __restrict__ idx,
                                                     int kk, int j, int npad){
    int i = blockIdx.x*256 + threadIdx.x;
    int p = i ^ j;
    if (i < npad && p > i && p < npad){
        bool up = ((i & kk) == 0);
        float ka = key[i], kb = key[p];
        int ia = idx[i], ib = idx[p];
        bool sw = up ? cmp_before(kb, ib, ka, ia) : cmp_before(ka, ia, kb, ib);
        if (sw){ key[i]=kb; idx[i]=ib; key[p]=ka; idx[p]=ia; }
    }
}

__global__ void __launch_bounds__(1024) k_merge_local(float* __restrict__ key, int* __restrict__ idx, int kk){
    __shared__ float sk[2048];
    __shared__ int   si[2048];
    int base = blockIdx.x * 2048;
    for (int t = threadIdx.x; t < 2048; t += 1024){ sk[t] = key[base+t]; si[t] = idx[base+t]; }
    __syncthreads();
    for (int j = 1024; j > 0; j >>= 1){
        for (int t = threadIdx.x; t < 2048; t += 1024){
            int p = t ^ j;
            if (p > t){
                bool up = (((base + t) & kk) == 0);
                float ka = sk[t], kb = sk[p];
                int ia = si[t], ib = si[p];
                bool sw = up ? cmp_before(kb, ib, ka, ia) : cmp_before(ka, ia, kb, ib);
                if (sw){ sk[t]=kb; si[t]=ib; sk[p]=ka; si[p]=ia; }
            }
        }
        __syncthreads();
    }
    for (int t = threadIdx.x; t < 2048; t += 1024){ key[base+t] = sk[t]; idx[base+t] = si[t]; }
}

// ---------------- gathers ----------------
__global__ void k_gather1(){
    int i = blockIdx.x*blockDim.x + threadIdx.x;
    if (i < NANCH){
        int id = g_idx1[i];
        ((float4*)g_sbox1)[i] = ((const float4*)g_boxes)[id];
    }
}

__global__ void k_gather2(){
    int i = blockIdx.x*blockDim.x + threadIdx.x;
    if (i < KP){
        int id = g_idx2[i];
        ((float4*)g_sdet)[i] = ((const float4*)g_dets)[id];
    }
}

// ---------------- NMS mask build (triangle skip + div skip) ----------------
__global__ void __launch_bounds__(64) k_mask(const float* __restrict__ sbox, int n, int nbw,
                                             unsigned long long* __restrict__ mask, float thr){
    int ib = blockIdx.y, jb = blockIdx.x;
    if (jb < ib) return;
    __shared__ float4 cb[64];
    __shared__ float  ca[64];
    int cj = jb*64 + threadIdx.x;
    if (cj < n){
        float4 b = ((const float4*)sbox)[cj];
        cb[threadIdx.x] = b;
        ca[threadIdx.x] = __fmul_rn(__fadd_rn(__fsub_rn(b.z,b.x),1.f), __fadd_rn(__fsub_rn(b.w,b.y),1.f));
    } else {
        cb[threadIdx.x] = make_float4(0,0,0,0);
        ca[threadIdx.x] = 1.f;
    }
    __syncthreads();
    int r = ib*64 + threadIdx.x;
    if (r >= n) return;
    float4 rb = ((const float4*)sbox)[r];
    float ra = __fmul_rn(__fadd_rn(__fsub_rn(rb.z,rb.x),1.f), __fadd_rn(__fsub_rn(rb.w,rb.y),1.f));
    unsigned long long m = 0;
    if (jb*64 + 63 > r){
        #pragma unroll 4
        for (int b = 0; b < 64; b++){
            int j = jb*64 + b;
            if (j > r && j < n){
                float4 o = cb[b];
                float xx1 = fmaxf(rb.x, o.x), yy1 = fmaxf(rb.y, o.y);
                float xx2 = fminf(rb.z, o.z), yy2 = fminf(rb.w, o.w);
                float iw = fmaxf(__fadd_rn(__fsub_rn(xx2,xx1),1.f), 0.f);
                float ih = fmaxf(__fadd_rn(__fsub_rn(yy2,yy1),1.f), 0.f);
                float inter = __fmul_rn(iw, ih);
                if (inter > 0.f){
                    float iou = __fdiv_rn(inter, __fsub_rn(__fadd_rn(ra, ca[b]), inter));
                    if (iou > thr) m |= (1ULL << b);
                }
            }
        }
    }
    mask[(size_t)r*nbw + jb] = m;
}

// ---------------- NMS scans (single warp, 4-deep prefetch) ----------------
__device__ __forceinline__ void nms_load1(int i, unsigned long long (&buf)[5], int lane){
    #pragma unroll
    for (int q = 0; q < 5; q++){
        int wq = q*32 + lane;
        buf[q] = (i < NANCH && wq < NBW1) ? g_mask1[(size_t)i*NBW1 + wq] : 0ULL;
    }
}
__device__ __forceinline__ bool nms_step1(int i, unsigned long long (&buf)[5],
                                          unsigned long long (&remv)[5], int lane, int &cnt){
    int w = i >> 6, slot = w >> 5, owner = w & 31;
    unsigned long long myw = slot==0?remv[0]:slot==1?remv[1]:slot==2?remv[2]:slot==3?remv[3]:remv[4];
    unsigned long long cur = __shfl_sync(0xffffffffu, myw, owner);
    if (!((cur >> (i & 63)) & 1ULL)){
        if (lane == 0 && cnt < KP) g_keep1[cnt] = g_idx1[i];
        cnt++;
        if (cnt >= KP) return true;
        #pragma unroll
        for (int q = 0; q < 5; q++) remv[q] |= buf[q];
    }
    return false;
}
__global__ void k_scan1(){
    int lane = threadIdx.x;
    unsigned long long remv[5] = {0,0,0,0,0};
    unsigned long long b0[5], b1[5], b2[5], b3[5];
    int cnt = 0;
    nms_load1(0,b0,lane); nms_load1(1,b1,lane); nms_load1(2,b2,lane); nms_load1(3,b3,lane);
    for (int i = 0; i < NANCH; i += 4){
        if (nms_step1(i+0, b0, remv, lane, cnt)) break;
        nms_load1(i+4, b0, lane);
        if (nms_step1(i+1, b1, remv, lane, cnt)) break;
        nms_load1(i+5, b1, lane);
        if (nms_step1(i+2, b2, remv, lane, cnt)) break;
        nms_load1(i+6, b2, lane);
        if (nms_step1(i+3, b3, remv, lane, cnt)) break;
        nms_load1(i+7, b3, lane);
    }
    for (int t = cnt + lane; t < KP; t += 32) g_keep1[t] = 0;
}

__device__ __forceinline__ bool nms_step2(int i, unsigned long long buf,
                                          unsigned long long &remv, int lane, int &cnt){
    int w = i >> 6;
    unsigned long long cur = __shfl_sync(0xffffffffu, remv, w);
    if (!((cur >> (i & 63)) & 1ULL)){
        if (lane == 0 && cnt < KP) g_keep2[cnt] = g_idx2[i];
        cnt++;
        if (cnt >= KP) return true;
        remv |= buf;
    }
    return false;
}
__global__ void k_scan2(){
    int lane = threadIdx.x;
    unsigned long long remv = 0;
    unsigned long long b0, b1, b2, b3;
    int cnt = 0;
    b0 = g_mask2[(size_t)0*NBW2 + lane];
    b1 = g_mask2[(size_t)1*NBW2 + lane];
    b2 = g_mask2[(size_t)2*NBW2 + lane];
    b3 = g_mask2[(size_t)3*NBW2 + lane];
    for (int i = 0; i < KP; i += 4){
        if (nms_step2(i+0, b0, remv, lane, cnt)) break;
        b0 = (i+4 < KP) ? g_mask2[(size_t)(i+4)*NBW2 + lane] : 0ULL;
        if (nms_step2(i+1, b1, remv, lane, cnt)) break;
        b1 = (i+5 < KP) ? g_mask2[(size_t)(i+5)*NBW2 + lane] : 0ULL;
        if (nms_step2(i+2, b2, remv, lane, cnt)) break;
        b2 = (i+6 < KP) ? g_mask2[(size_t)(i+6)*NBW2 + lane] : 0ULL;
        if (nms_step2(i+3, b3, remv, lane, cnt)) break;
        b3 = (i+7 < KP) ? g_mask2[(size_t)(i+7)*NBW2 + lane] : 0ULL;
    }
    if (lane == 0) g_nk2 = cnt;
    for (int t = cnt + lane; t < KP; t += 32) g_keep2[t] = 0;
}

// ---------------- proposals ----------------
__global__ void k_props(float* __restrict__ out){
    int i = blockIdx.x*blockDim.x + threadIdx.x;
    if (i < KP){
        int id = g_keep1[i];
        float4 b = ((const float4*)g_boxes)[id];
        out[O_PROPS + i*4+0] = b.x; out[O_PROPS + i*4+1] = b.y;
        out[O_PROPS + i*4+2] = b.z; out[O_PROPS + i*4+3] = b.w;
        ((float4*)g_prop4)[i] = b;
        g_nbox[i*4+0] = __fdiv_rn(b.y, 511.f);
        g_nbox[i*4+1] = __fdiv_rn(b.x, 511.f);
        g_nbox[i*4+2] = __fdiv_rn(b.w, 511.f);
        g_nbox[i*4+3] = __fdiv_rn(b.z, 511.f);
    }
}

// ---------------- crop + bilinear + 2x2 maxpool ----------------
__global__ void __launch_bounds__(256) k_crop(){
    int k = blockIdx.x;
    int warp = threadIdx.x >> 5, lane = threadIdx.x & 31;
    float y1 = g_nbox[k*4+0], x1 = g_nbox[k*4+1], y2 = g_nbox[k*4+2], x2 = g_nbox[k*4+3];
    float dy = __fsub_rn(y2, y1), dx = __fsub_rn(x2, x1);
    int c4 = lane*4;
    const float4* f = (const float4*)g_featT;
    for (int p = warp; p < 49; p += 8){
        int oi = p/7, oj = p%7;
        float4 acc = make_float4(-1e30f,-1e30f,-1e30f,-1e30f);
        #pragma unroll
        for (int di = 0; di < 2; di++){
            #pragma unroll
            for (int dj = 0; dj < 2; dj++){
                int ti = 2*oi+di, tj = 2*oj+dj;
                float ty = __fdiv_rn((float)ti, 13.f);
                float tx = __fdiv_rn((float)tj, 13.f);
                float ys = __fmul_rn(__fadd_rn(y1, __fmul_rn(ty, dy)), 31.f);
                float xs = __fmul_rn(__fadd_rn(x1, __fmul_rn(tx, dx)), 31.f);
                int y0 = min(max((int)floorf(ys), 0), 31);
                int y1i = min(y0+1, 31);
                int x0 = min(max((int)floorf(xs), 0), 31);
                int x1i = min(x0+1, 31);
                float wy = __fsub_rn(ys, (float)y0);
                float wx = __fsub_rn(xs, (float)x0);
                float omwx = __fsub_rn(1.f, wx), omwy = __fsub_rn(1.f, wy);
                float4 f00 = f[((y0*32+x0)*128 + c4) >> 2];
                float4 f01 = f[((y0*32+x1i)*128 + c4) >> 2];
                float4 f10 = f[((y1i*32+x0)*128 + c4) >> 2];
                float4 f11 = f[((y1i*32+x1i)*128 + c4) >> 2];
                #pragma unroll
                for (int e = 0; e < 4; e++){
                    float a00 = (&f00.x)[e], a01 = (&f01.x)[e];
                    float a10 = (&f10.x)[e], a11 = (&f11.x)[e];
                    float top = __fadd_rn(__fmul_rn(a00, omwx), __fmul_rn(a01, wx));
                    float bot = __fadd_rn(__fmul_rn(a10, omwx), __fmul_rn(a11, wx));
                    float val = __fadd_rn(__fmul_rn(top, omwy), __fmul_rn(bot, wy));
                    (&acc.x)[e] = fmaxf((&acc.x)[e], val);
                }
            }
        }
        ((float4*)g_flat)[((size_t)k*FK + p*128 + c4) >> 2] = acc;
    }
}

// ---------------- fp32 SIMT GEMM: 128x128 tile, 8x8 micro, double-buffered ----------------
#define GP 132
__global__ void __launch_bounds__(256) k_gemm(const float* __restrict__ A, const float* __restrict__ B,
                                              const float* __restrict__ bias, float* __restrict__ Cmat,
                                              int M, int N, int K){
    __shared__ float As[2][16][GP];
    __shared__ float Bs[2][16][GP];
    int tid = threadIdx.x;
    int tx = tid & 15, ty = tid >> 4;
    int mbase = blockIdx.y*128, nbase = blockIdx.x*128;
    float acc[8][8];
    #pragma unroll
    for (int r = 0; r < 8; r++)
        #pragma unroll
        for (int q = 0; q < 8; q++) acc[r][q] = 0.f;

    int r0 = tid >> 2,          c0 = (tid & 3) * 4;
    int r1 = (tid + 256) >> 2,  c1 = ((tid + 256) & 3) * 4;
    const float* Ap0 = A + (size_t)(mbase + r0)*K + c0;
    const float* Ap1 = A + (size_t)(mbase + r1)*K + c1;
    const float* Bp0 = B + (size_t)(nbase + r0)*K + c0;
    const float* Bp1 = B + (size_t)(nbase + r1)*K + c1;
    bool av0 = (mbase + r0) < M, av1 = (mbase + r1) < M;

    float4 a0 = av0 ? *(const float4*)Ap0 : make_float4(0,0,0,0);
    float4 a1 = av1 ? *(const float4*)Ap1 : make_float4(0,0,0,0);
    float4 b0 = *(const float4*)Bp0;
    float4 b1 = *(const float4*)Bp1;
    As[0][c0+0][r0]=a0.x; As[0][c0+1][r0]=a0.y; As[0][c0+2][r0]=a0.z; As[0][c0+3][r0]=a0.w;
    As[0][c1+0][r1]=a1.x; As[0][c1+1][r1]=a1.y; As[0][c1+2][r1]=a1.z; As[0][c1+3][r1]=a1.w;
    Bs[0][c0+0][r0]=b0.x; Bs[0][c0+1][r0]=b0.y; Bs[0][c0+2][r0]=b0.z; Bs[0][c0+3][r0]=b0.w;
    Bs[0][c1+0][r1]=b1.x; Bs[0][c1+1][r1]=b1.y; Bs[0][c1+2][r1]=b1.z; Bs[0][c1+3][r1]=b1.w;
    __syncthreads();

    int nIter = K / 16;
    for (int it = 0; it < nIter; it++){
        int buf = it & 1;
        float4 na0, na1, nb0, nb1;
        if (it + 1 < nIter){
            int koff = (it+1)*16;
            na0 = av0 ? *(const float4*)(Ap0 + koff) : make_float4(0,0,0,0);
            na1 = av1 ? *(const float4*)(Ap1 + koff) : make_float4(0,0,0,0);
            nb0 = *(const float4*)(Bp0 + koff);
            nb1 = *(const float4*)(Bp1 + koff);
        }
        #pragma unroll
        for (int kk = 0; kk < 16; kk++){
            float ar[8], br[8];
            *(float4*)(ar)   = *(const float4*)&As[buf][kk][ty*8];
            *(float4*)(ar+4) = *(const float4*)&As[buf][kk][ty*8+4];
            *(float4*)(br)   = *(const float4*)&Bs[buf][kk][tx*8];
            *(float4*)(br+4) = *(const float4*)&Bs[buf][kk][tx*8+4];
            #pragma unroll
            for (int r = 0; r < 8; r++)
                #pragma unroll
                for (int q = 0; q < 8; q++)
                    acc[r][q] = fmaf(ar[r], br[q], acc[r][q]);
        }
        if (it + 1 < nIter){
            int nb = buf ^ 1;
            __syncthreads();
            As[nb][c0+0][r0]=na0.x; As[nb][c0+1][r0]=na0.y; As[nb][c0+2][r0]=na0.z; As[nb][c0+3][r0]=na0.w;
            As[nb][c1+0][r1]=na1.x; As[nb][c1+1][r1]=na1.y; As[nb][c1+2][r1]=na1.z; As[nb][c1+3][r1]=na1.w;
            Bs[nb][c0+0][r0]=nb0.x; Bs[nb][c0+1][r0]=nb0.y; Bs[nb][c0+2][r0]=nb0.z; Bs[nb][c0+3][r0]=nb0.w;
            Bs[nb][c1+0][r1]=nb1.x; Bs[nb][c1+1][r1]=nb1.y; Bs[nb][c1+2][r1]=nb1.z; Bs[nb][c1+3][r1]=nb1.w;
            __syncthreads();
        }
    }
    #pragma unroll
    for (int r = 0; r < 8; r++){
        int row = mbase + ty*8 + r;
        if (row < M){
            #pragma unroll
            for (int q = 0; q < 8; q++){
                int col = nbase + tx*8 + q;
                Cmat[(size_t)row*N + col] = fmaxf(__fadd_rn(acc[r][q], bias[col]), 0.f);
            }
        }
    }
}

// ---------------- RCNN heads + decode2 (fp64 dots — cheap, keep proven path) ----------------
__global__ void __launch_bounds__(192) k_heads(const float* __restrict__ cw, const float* __restrict__ cb,
                                               const float* __restrict__ rw, const float* __restrict__ rb,
                                               float* __restrict__ out){
    __shared__ float sd[6];
    int k = blockIdx.x;
    int warp = threadIdx.x >> 5, lane = threadIdx.x & 31;
    const float4* h4 = (const float4*)(g_h2 + (size_t)k*1024);
    const float4* w4 = (const float4*)((warp < 2) ? (cw + warp*1024) : (rw + (warp-2)*1024));
    double acc = 0.0;
    #pragma unroll
    for (int q = 0; q < 8; q++){
        float4 a = h4[lane + q*32], b = w4[lane + q*32];
        acc = fma((double)a.x, (double)b.x, acc);
        acc = fma((double)a.y, (double)b.y, acc);
        acc = fma((double)a.z, (double)b.z, acc);
        acc = fma((double)a.w, (double)b.w, acc);
    }
    #pragma unroll
    for (int o = 16; o; o >>= 1) acc += __shfl_xor_sync(0xffffffffu, acc, o);
    if (lane == 0) sd[warp] = __fadd_rn((float)acc, (warp < 2) ? cb[warp] : rb[warp-2]);
    __syncthreads();
    if (threadIdx.x == 0){
        float l0 = sd[0], l1 = sd[1];
        out[O_RCL + k*2+0] = l0; out[O_RCL + k*2+1] = l1;
        float d0 = sd[2], d1 = sd[3], d2 = sd[4], d3 = sd[5];
        out[O_RCD + k*4+0]=d0; out[O_RCD + k*4+1]=d1;
        out[O_RCD + k*4+2]=d2; out[O_RCD + k*4+3]=d3;
        float score = softmax1(l0, l1);
        float4 pr = ((const float4*)g_prop4)[k];
        float w = __fadd_rn(__fsub_rn(pr.z, pr.x), 1.f);
        float h = __fadd_rn(__fsub_rn(pr.w, pr.y), 1.f);
        float ccx = __fadd_rn(pr.x, __fmul_rn(0.5f, w));
        float ccy = __fadd_rn(pr.y, __fmul_rn(0.5f, h));
        float pcx = __fadd_rn(__fmul_rn(d0, w), ccx);
        float pcy = __fadd_rn(__fmul_rn(d1, h), ccy);
        float pw = __fmul_rn(exp_strict(d2), w);
        float ph = __fmul_rn(exp_strict(d3), h);
        float hw = __fmul_rn(0.5f, pw), hh = __fmul_rn(0.5f, ph);
        float4 dt;
        dt.x = fminf(fmaxf(__fsub_rn(pcx, hw), 0.f), 511.f);
        dt.y = fminf(fmaxf(__fsub_rn(pcy, hh), 0.f), 511.f);
        dt.z = fminf(fmaxf(__fadd_rn(pcx, hw), 0.f), 511.f);
        dt.w = fminf(fmaxf(__fadd_rn(pcy, hh), 0.f), 511.f);
        ((float4*)g_dets)[k] = dt;
        g_rsc[k] = score;
        g_key2[k] = score;
        g_idx2[k] = k;
    }
}

// ---------------- final outputs ----------------
__global__ void k_final(float* __restrict__ out){
    int i = blockIdx.x*blockDim.x + threadIdx.x;
    if (i < KP){
        float m = (i < g_nk2) ? 1.f : 0.f;
        int id = g_keep2[i];
        float4 d = ((const float4*)g_dets)[id];
        out[O_DETS + i*4+0] = d.x*m; out[O_DETS + i*4+1] = d.y*m;
        out[O_DETS + i*4+2] = d.z*m; out[O_DETS + i*4+3] = d.w*m;
        out[O_SC + i] = g_rsc[id]*m;
    }
}

// ---------------- launch ----------------
extern "C" void kernel_launch(void* const* d_in, const int* in_sizes, int n_in,
                              void* d_out, int out_size){
    const float* x        = (const float*)d_in[0];
    const float* bb_w     = (const float*)d_in[1];
    const float* bb_b     = (const float*)d_in[2];
    const float* rpn_w    = (const float*)d_in[3];
    const float* rpn_b    = (const float*)d_in[4];
    const float* rpn_cls_w= (const float*)d_in[5];
    const float* rpn_cls_b= (const float*)d_in[6];
    const float* rpn_reg_w= (const float*)d_in[7];
    const float* rpn_reg_b= (const float*)d_in[8];
    const float* fc1_w    = (const float*)d_in[9];
    const float* fc1_b    = (const float*)d_in[10];
    const float* fc2_w    = (const float*)d_in[11];
    const float* fc2_b    = (const float*)d_in[12];
    const float* cls_w    = (const float*)d_in[13];
    const float* cls_b    = (const float*)d_in[14];
    const float* reg_w    = (const float*)d_in[15];
    const float* reg_b    = (const float*)d_in[16];
    float* out = (float*)d_out;

    float *p_key1, *p_key2, *p_sbox1, *p_sdet, *p_flat, *p_fc1wP, *p_h1, *p_h2;
    int *p_idx1, *p_idx2;
    unsigned long long *p_mask1, *p_mask2;
    cudaGetSymbolAddress((void**)&p_key1,  g_key1);
    cudaGetSymbolAddress((void**)&p_idx1,  g_idx1);
    cudaGetSymbolAddress((void**)&p_key2,  g_key2);
    cudaGetSymbolAddress((void**)&p_idx2,  g_idx2);
    cudaGetSymbolAddress((void**)&p_sbox1, g_sbox1);
    cudaGetSymbolAddress((void**)&p_sdet,  g_sdet);
    cudaGetSymbolAddress((void**)&p_mask1, g_mask1);
    cudaGetSymbolAddress((void**)&p_mask2, g_mask2);
    cudaGetSymbolAddress((void**)&p_flat,  g_flat);
    cudaGetSymbolAddress((void**)&p_fc1wP, g_fc1wP);
    cudaGetSymbolAddress((void**)&p_h1,    g_h1);
    cudaGetSymbolAddress((void**)&p_h2,    g_h2);

    k_transpose<<<(768*128+255)/256, 256>>>(bb_w, 768, 0);
    k_transpose<<<(1152*128+255)/256, 256>>>(rpn_w, 1152, 1);
    k_tfc1<<<1024, 256>>>(fc1_w);
    k_init<<<32, 256>>>();

    k_conv1<<<256, 128>>>(x, bb_b);
    k_conv2<<<256, 128>>>(rpn_b);
    k_rpn<<<1024, 64>>>(rpn_cls_w, rpn_cls_b, rpn_reg_w, rpn_reg_b, out);

    // hybrid bitonic sort over 16384 (desc score, tie idx asc)
    k_sort_local<<<8, 1024>>>(p_key1, p_idx1);
    for (int kk = 4096; kk <= NPAD1; kk <<= 1){
        for (int j = kk >> 1; j >= 2048; j >>= 1)
            k_sort_global<<<NPAD1/256, 256>>>(p_key1, p_idx1, kk, j, NPAD1);
        k_merge_local<<<8, 1024>>>(p_key1, p_idx1, kk);
    }

    k_gather1<<<(NANCH+255)/256, 256>>>();
    {
        dim3 g(NBW1, NBW1);
        k_mask<<<g, 64>>>(p_sbox1, NANCH, NBW1, p_mask1, 0.5f);
    }
    k_scan1<<<1, 32>>>();
    k_props<<<(KP+255)/256, 256>>>(out);
    k_crop<<<KP, 256>>>();

    {
        dim3 g1(8, 16);
        k_gemm<<<g1, 256>>>(p_flat, p_fc1wP, fc1_b, p_h1, KP, 1024, FK);
        k_gemm<<<g1, 256>>>(p_h1, fc2_w, fc2_b, p_h2, KP, 1024, 1024);
    }
    k_heads<<<KP, 192>>>(cls_w, cls_b, reg_w, reg_b, out);

    k_sort_local<<<1, 1024>>>(p_key2, p_idx2);

    k_gather2<<<(KP+255)/256, 256>>>();
    {
        dim3 g(NBW2, NBW2);
        k_mask<<<g, 64>>>(p_sdet, KP, NBW2, p_mask2, 0.3f);
    }
    k_scan2<<<1, 32>>>();
    k_final<<<(KP+255)/256, 256>>>(out);
}

// round 14
// speedup vs baseline: 1.9300x; 1.0335x over previous
#include <cuda_runtime.h>
#include <math.h>

#define NANCH 9216
#define NPAD1 16384
#define NBW1  144
#define KP    2000
#define NPAD2 2048
#define NBW2  32
#define FK    6272
#define FULLM 0xffffffffu

// output offsets (floats)
#define O_RPNL  0
#define O_RPND  18432
#define O_PROPS 55296
#define O_ANCH  63296
#define O_RCL   100160
#define O_RCD   104160
#define O_DETS  112160
#define O_SC    120160

// ---------------- device scratch ----------------
__device__ __align__(16) float g_featT[32*32*128];
__device__ __align__(16) float g_hT[32*32*128];
__device__ __align__(16) float g_bbT[768*128];
__device__ __align__(16) float g_rwT[1152*128];
__device__ __align__(16) float g_fc1wP[1024*FK];
__device__ __align__(16) float g_boxes[NANCH*4];
__device__ float g_key1[NPAD1];
__device__ int   g_idx1[NPAD1];
__device__ __align__(16) float g_sbox1[NANCH*4];
__device__ unsigned long long g_mask1[(size_t)NANCH*NBW1];
__device__ int   g_keep1[KP];
__device__ __align__(16) float g_prop4[KP*4];
__device__ __align__(16) float g_nbox[KP*4];
__device__ __align__(16) float g_flat[(size_t)KP*FK];
__device__ __align__(16) float g_h1[KP*1024];
__device__ __align__(16) float g_h2[KP*1024];
__device__ float g_rsc[KP];
__device__ __align__(16) float g_dets[KP*4];
__device__ float g_key2[NPAD2];
__device__ int   g_idx2[NPAD2];
__device__ __align__(16) float g_sdet[KP*4];
__device__ unsigned long long g_mask2[(size_t)KP*NBW2];
__device__ int   g_keep2[KP];
__device__ int   g_nk2;

// fast-math-immune, correctly-rounded fp32 exp (double exp is never remapped)
__device__ __forceinline__ float exp_strict(float x){
    return (float)exp((double)x);
}

// exact mirror of jax.nn.softmax([l0,l1])[1] in fp32, fast-math-immune
__device__ __forceinline__ float softmax1(float l0, float l1){
    float m = fmaxf(l0, l1);
    float e0 = exp_strict(__fsub_rn(l0, m));
    float e1 = exp_strict(__fsub_rn(l1, m));
    return __fdiv_rn(e1, __fadd_rn(e0, e1));
}

// Compensated (double-float) accumulate: s+c += a*w with ~1e-9 relative error.
#define DF_ACC(a, w, s, c) { \
    float _p = __fmul_rn((a), (w)); \
    float _e = __fmaf_rn((a), (w), -_p); \
    float _t = __fadd_rn((s), _p); \
    float _z = __fsub_rn(_t, (s)); \
    float _e2 = __fadd_rn(__fsub_rn(_p, _z), __fsub_rn((s), __fsub_rn(_t, _z))); \
    (s) = _t; \
    (c) = __fadd_rn((c), __fadd_rn(_e, _e2)); \
}

// ---------------- weight permutes ----------------
__global__ void k_transpose(const float* __restrict__ src, int K, int which){
    float* dst = which ? g_rwT : g_bbT;
    int t = blockIdx.x*blockDim.x + threadIdx.x;
    if (t < K*128){
        int i = t >> 7, c = t & 127;
        dst[t] = src[c*K + i];
    }
}

__global__ void __launch_bounds__(256) k_tfc1(const float* __restrict__ w){
    __shared__ float s[FK];
    int h = blockIdx.x;
    const float* src = w + (size_t)h*FK;
    for (int t = threadIdx.x; t < FK; t += 256) s[t] = src[t];
    __syncthreads();
    float* dst = g_fc1wP + (size_t)h*FK;
    for (int t = threadIdx.x; t < FK; t += 256){
        int p = t >> 7, c = t & 127;
        dst[t] = s[c*49 + p];
    }
}

__global__ void k_init(){
    int t = blockIdx.x*blockDim.x + threadIdx.x;
    if (t < NPAD1 - NANCH){ g_key1[NANCH+t] = -1.f; g_idx1[NANCH+t] = 0x7fffffff; }
    if (t < NPAD2 - KP)   { g_key2[KP+t]    = -1.f; g_idx2[KP+t]    = 0x7fffffff; }
}

// ---------------- conv1: 3->128, 16x16 stride16 VALID, relu (compensated fp32) ----------------
__global__ void __launch_bounds__(128) k_conv1(const float* __restrict__ x, const float* __restrict__ bias){
    __shared__ float sp[4*768];
    int gy  = blockIdx.x >> 3;
    int gx0 = (blockIdx.x & 7) * 4;
    int tid = threadIdx.x;
    for (int e = tid; e < 3072; e += 128){
        int spx = e / 768, i = e % 768;
        int ci = i >> 8, rr = i & 255, ky = rr >> 4, kx = rr & 15;
        sp[e] = x[ci*(512*512) + (gy*16+ky)*512 + (gx0+spx)*16 + kx];
    }
    __syncthreads();
    float s0=0.f,c0=0.f, s1=0.f,c1=0.f, s2=0.f,c2=0.f, s3=0.f,c3=0.f;
    for (int i = 0; i < 768; i++){
        float w = g_bbT[i*128 + tid];
        DF_ACC(sp[i],      w, s0, c0);
        DF_ACC(sp[768+i],  w, s1, c1);
        DF_ACC(sp[1536+i], w, s2, c2);
        DF_ACC(sp[2304+i], w, s3, c3);
    }
    float b = bias[tid];
    int base = (gy*32 + gx0)*128 + tid;
    g_featT[base      ] = fmaxf(__fadd_rn(__fadd_rn(s0, c0), b), 0.f);
    g_featT[base + 128] = fmaxf(__fadd_rn(__fadd_rn(s1, c1), b), 0.f);
    g_featT[base + 256] = fmaxf(__fadd_rn(__fadd_rn(s2, c2), b), 0.f);
    g_featT[base + 384] = fmaxf(__fadd_rn(__fadd_rn(s3, c3), b), 0.f);
}

// ---------------- conv2: 3x3 SAME 128->128, relu (compensated fp32) ----------------
__global__ void __launch_bounds__(128) k_conv2(const float* __restrict__ bias){
    __shared__ float sp[18*128];
    int gy  = blockIdx.x >> 3;
    int gx0 = (blockIdx.x & 7) * 4;
    int tid = threadIdx.x;
    for (int e = tid; e < 18*128; e += 128){
        int pix = e >> 7, ci = e & 127;
        int ky = pix / 6, sx = pix % 6;
        int iy = gy + ky - 1, ix = gx0 + sx - 1;
        float v = 0.f;
        if (iy >= 0 && iy < 32 && ix >= 0 && ix < 32) v = g_featT[(iy*32+ix)*128 + ci];
        sp[e] = v;
    }
    __syncthreads();
    float s0=0.f,c0=0.f, s1=0.f,c1=0.f, s2=0.f,c2=0.f, s3=0.f,c3=0.f;
    int i = 0;
    for (int ci = 0; ci < 128; ci++){
        #pragma unroll
        for (int ky = 0; ky < 3; ky++){
            #pragma unroll
            for (int kx = 0; kx < 3; kx++){
                float w = g_rwT[i*128 + tid];
                int base = (ky*6+kx)*128 + ci;
                DF_ACC(sp[base      ], w, s0, c0);
                DF_ACC(sp[base + 128], w, s1, c1);
                DF_ACC(sp[base + 256], w, s2, c2);
                DF_ACC(sp[base + 384], w, s3, c3);
                i++;
            }
        }
    }
    float b = bias[tid];
    int ob = (gy*32+gx0)*128 + tid;
    g_hT[ob      ] = fmaxf(__fadd_rn(__fadd_rn(s0, c0), b), 0.f);
    g_hT[ob + 128] = fmaxf(__fadd_rn(__fadd_rn(s1, c1), b), 0.f);
    g_hT[ob + 256] = fmaxf(__fadd_rn(__fadd_rn(s2, c2), b), 0.f);
    g_hT[ob + 384] = fmaxf(__fadd_rn(__fadd_rn(s3, c3), b), 0.f);
}

// ---------------- RPN heads + softmax + anchors + decode + clip (compensated fp32 dots) ----------------
__global__ void __launch_bounds__(64) k_rpn(const float* __restrict__ cw, const float* __restrict__ cb,
                                            const float* __restrict__ rw, const float* __restrict__ rb,
                                            float* __restrict__ out){
    __shared__ float sh[128];
    __shared__ float sd[54];
    int pix = blockIdx.x;
    int tid = threadIdx.x;
    sh[tid]      = g_hT[pix*128 + tid];
    sh[tid + 64] = g_hT[pix*128 + tid + 64];
    __syncthreads();
    if (tid < 54){
        const float* wrow = (tid < 18) ? (cw + tid*128) : (rw + (tid-18)*128);
        float bb = (tid < 18) ? cb[tid] : rb[tid-18];
        float s = 0.f, c = 0.f;
        for (int cc = 0; cc < 128; cc++){
            DF_ACC(sh[cc], wrow[cc], s, c);
        }
        sd[tid] = __fadd_rn(__fadd_rn(s, c), bb);
    }
    __syncthreads();
    if (tid < 9){
        int a = tid;
        int y = pix >> 5, x = pix & 31;
        int n = pix*9 + a;
        float l0 = sd[2*a], l1 = sd[2*a+1];
        out[O_RPNL + n*2+0] = l0; out[O_RPNL + n*2+1] = l1;
        float d0 = sd[18+4*a+0], d1 = sd[18+4*a+1], d2 = sd[18+4*a+2], d3 = sd[18+4*a+3];
        out[O_RPND + n*4+0]=d0; out[O_RPND + n*4+1]=d1;
        out[O_RPND + n*4+2]=d2; out[O_RPND + n*4+3]=d3;
        const float scv[3] = {32.f, 64.f, 128.f};
        const float rv[3]  = {0.5f, 1.f, 2.f};
        int si = a/3, ri = a%3;
        float sr = __fsqrt_rn(rv[ri]);
        float ws = __fdiv_rn(scv[si], sr);
        float hs = __fmul_rn(scv[si], sr);
        float cx = __fmul_rn(__fadd_rn((float)x, 0.5f), 16.f);
        float cy = __fmul_rn(__fadd_rn((float)y, 0.5f), 16.f);
        float W2 = __fmul_rn(ws, 0.5f);
        float H2 = __fmul_rn(hs, 0.5f);
        float ax1 = __fsub_rn(cx, W2), ay1 = __fsub_rn(cy, H2);
        float ax2 = __fadd_rn(cx, W2), ay2 = __fadd_rn(cy, H2);
        out[O_ANCH + n*4+0]=ax1; out[O_ANCH + n*4+1]=ay1;
        out[O_ANCH + n*4+2]=ax2; out[O_ANCH + n*4+3]=ay2;
        float w = __fadd_rn(__fsub_rn(ax2, ax1), 1.f);
        float h = __fadd_rn(__fsub_rn(ay2, ay1), 1.f);
        float ccx = __fadd_rn(ax1, __fmul_rn(0.5f, w));
        float ccy = __fadd_rn(ay1, __fmul_rn(0.5f, h));
        float pcx = __fadd_rn(__fmul_rn(d0, w), ccx);
        float pcy = __fadd_rn(__fmul_rn(d1, h), ccy);
        float pw = __fmul_rn(exp_strict(d2), w);
        float ph = __fmul_rn(exp_strict(d3), h);
        float hw = __fmul_rn(0.5f, pw), hh = __fmul_rn(0.5f, ph);
        g_boxes[n*4+0] = fminf(fmaxf(__fsub_rn(pcx, hw), 0.f), 511.f);
        g_boxes[n*4+1] = fminf(fmaxf(__fsub_rn(pcy, hh), 0.f), 511.f);
        g_boxes[n*4+2] = fminf(fmaxf(__fadd_rn(pcx, hw), 0.f), 511.f);
        g_boxes[n*4+3] = fminf(fmaxf(__fadd_rn(pcy, hh), 0.f), 511.f);
        g_key1[n] = softmax1(l0, l1);
        g_idx1[n] = n;
    }
}

// ---------------- hybrid bitonic sort (desc score, tie idx asc) ----------------
__device__ __forceinline__ bool cmp_before(float ka, int ia, float kb, int ib){
    return (ka > kb) || (ka == kb && ia < ib);
}

__global__ void __launch_bounds__(1024) k_sort_local(float* __restrict__ key, int* __restrict__ idx){
    __shared__ float sk[2048];
    __shared__ int   si[2048];
    int base = blockIdx.x * 2048;
    for (int t = threadIdx.x; t < 2048; t += 1024){ sk[t] = key[base+t]; si[t] = idx[base+t]; }
    __syncthreads();
    for (int kk = 2; kk <= 2048; kk <<= 1){
        for (int j = kk >> 1; j > 0; j >>= 1){
            for (int t = threadIdx.x; t < 2048; t += 1024){
                int p = t ^ j;
                if (p > t){
                    bool up = (((base + t) & kk) == 0);
                    float ka = sk[t], kb = sk[p];
                    int ia = si[t], ib = si[p];
                    bool sw = up ? cmp_before(kb, ib, ka, ia) : cmp_before(ka, ia, kb, ib);
                    if (sw){ sk[t]=kb; si[t]=ib; sk[p]=ka; si[p]=ia; }
                }
            }
            __syncthreads();
        }
    }
    for (int t = threadIdx.x; t < 2048; t += 1024){ key[base+t] = sk[t]; idx[base+t] = si[t]; }
}

__global__ void __launch_bounds__(256) k_sort_global(float* __restrict__ key, int* __restrict__ idx,
                                                     int kk, int j, int npad){
    int i = blockIdx.x*256 + threadIdx.x;
    int p = i ^ j;
    if (i < npad && p > i && p < npad){
        bool up = ((i & kk) == 0);
        float ka = key[i], kb = key[p];
        int ia = idx[i], ib = idx[p];
        bool sw = up ? cmp_before(kb, ib, ka, ia) : cmp_before(ka, ia, kb, ib);
        if (sw){ key[i]=kb; idx[i]=ib; key[p]=ka; idx[p]=ia; }
    }
}

__global__ void __launch_bounds__(1024) k_merge_local(float* __restrict__ key, int* __restrict__ idx, int kk){
    __shared__ float sk[2048];
    __shared__ int   si[2048];
    int base = blockIdx.x * 2048;
    for (int t = threadIdx.x; t < 2048; t += 1024){ sk[t] = key[base+t]; si[t] = idx[base+t]; }
    __syncthreads();
    for (int j = 1024; j > 0; j >>= 1){
        for (int t = threadIdx.x; t < 2048; t += 1024){
            int p = t ^ j;
            if (p > t){
                bool up = (((base + t) & kk) == 0);
                float ka = sk[t], kb = sk[p];
                int ia = si[t], ib = si[p];
                bool sw = up ? cmp_before(kb, ib, ka, ia) : cmp_before(ka, ia, kb, ib);
                if (sw){ sk[t]=kb; si[t]=ib; sk[p]=ka; si[p]=ia; }
            }
        }
        __syncthreads();
    }
    for (int t = threadIdx.x; t < 2048; t += 1024){ key[base+t] = sk[t]; idx[base+t] = si[t]; }
}

// ---------------- gathers ----------------
__global__ void k_gather1(){
    int i = blockIdx.x*blockDim.x + threadIdx.x;
    if (i < NANCH){
        int id = g_idx1[i];
        ((float4*)g_sbox1)[i] = ((const float4*)g_boxes)[id];
    }
}

__global__ void k_gather2(){
    int i = blockIdx.x*blockDim.x + threadIdx.x;
    if (i < KP){
        int id = g_idx2[i];
        ((float4*)g_sdet)[i] = ((const float4*)g_dets)[id];
    }
}

// ---------------- NMS mask build (triangle skip + div skip) ----------------
__global__ void __launch_bounds__(64) k_mask(const float* __restrict__ sbox, int n, int nbw,
                                             unsigned long long* __restrict__ mask, float thr){
    int ib = blockIdx.y, jb = blockIdx.x;
    if (jb < ib) return;
    __shared__ float4 cb[64];
    __shared__ float  ca[64];
    int cj = jb*64 + threadIdx.x;
    if (cj < n){
        float4 b = ((const float4*)sbox)[cj];
        cb[threadIdx.x] = b;
        ca[threadIdx.x] = __fmul_rn(__fadd_rn(__fsub_rn(b.z,b.x),1.f), __fadd_rn(__fsub_rn(b.w,b.y),1.f));
    } else {
        cb[threadIdx.x] = make_float4(0,0,0,0);
        ca[threadIdx.x] = 1.f;
    }
    __syncthreads();
    int r = ib*64 + threadIdx.x;
    if (r >= n) return;
    float4 rb = ((const float4*)sbox)[r];
    float ra = __fmul_rn(__fadd_rn(__fsub_rn(rb.z,rb.x),1.f), __fadd_rn(__fsub_rn(rb.w,rb.y),1.f));
    unsigned long long m = 0;
    if (jb*64 + 63 > r){
        #pragma unroll 4
        for (int b = 0; b < 64; b++){
            int j = jb*64 + b;
            if (j > r && j < n){
                float4 o = cb[b];
                float xx1 = fmaxf(rb.x, o.x), yy1 = fmaxf(rb.y, o.y);
                float xx2 = fminf(rb.z, o.z), yy2 = fminf(rb.w, o.w);
                float iw = fmaxf(__fadd_rn(__fsub_rn(xx2,xx1),1.f), 0.f);
                float ih = fmaxf(__fadd_rn(__fsub_rn(yy2,yy1),1.f), 0.f);
                float inter = __fmul_rn(iw, ih);
                if (inter > 0.f){
                    float iou = __fdiv_rn(inter, __fsub_rn(__fadd_rn(ra, ca[b]), inter));
                    if (iou > thr) m |= (1ULL << b);
                }
            }
        }
    }
    mask[(size_t)r*nbw + jb] = m;
}

// ---------------- NMS scan 1: cached current-word, shfl only on keep ----------------
__device__ __forceinline__ void nms_load1(int i, unsigned long long (&buf)[5], int lane){
    #pragma unroll
    for (int q = 0; q < 5; q++){
        int wq = q*32 + lane;
        buf[q] = (i < NANCH && wq < NBW1) ? g_mask1[(size_t)i*NBW1 + wq] : 0ULL;
    }
}
__device__ __forceinline__ unsigned long long sel5(const unsigned long long (&v)[5], int slot){
    return slot==0?v[0]:slot==1?v[1]:slot==2?v[2]:slot==3?v[3]:v[4];
}
// step: test cached cur; on keep, update remv and refresh cur via one shfl
__device__ __forceinline__ void nms_step1c(int i, unsigned long long (&buf)[5],
                                           unsigned long long (&remv)[5],
                                           unsigned long long &cur, int slot, int owner,
                                           int lane, int &cnt, bool &done){
    if (!((cur >> (i & 63)) & 1ULL)){
        if (lane == 0 && cnt < KP) g_keep1[cnt] = g_idx1[i];
        cnt++;
        if (cnt >= KP){ done = true; return; }
        #pragma unroll
        for (int q = 0; q < 5; q++) remv[q] |= buf[q];
        unsigned long long dw = sel5(buf, slot);
        cur |= __shfl_sync(FULLM, dw, owner);
    }
}
__global__ void k_scan1(){
    int lane = threadIdx.x;
    unsigned long long remv[5] = {0,0,0,0,0};
    unsigned long long b0[5], b1[5], b2[5], b3[5];
    int cnt = 0;
    bool done = false;
    nms_load1(0,b0,lane); nms_load1(1,b1,lane); nms_load1(2,b2,lane); nms_load1(3,b3,lane);
    for (int g = 0; g < NANCH/64 && !done; g++){
        int slot = g >> 5, owner = g & 31;
        unsigned long long cur = __shfl_sync(FULLM, sel5(remv, slot), owner);
        for (int c = 0; c < 16 && !done; c++){
            int i = g*64 + c*4;
            nms_step1c(i+0, b0, remv, cur, slot, owner, lane, cnt, done);
            if (done) break;
            nms_load1(i+4, b0, lane);
            nms_step1c(i+1, b1, remv, cur, slot, owner, lane, cnt, done);
            if (done) break;
            nms_load1(i+5, b1, lane);
            nms_step1c(i+2, b2, remv, cur, slot, owner, lane, cnt, done);
            if (done) break;
            nms_load1(i+6, b2, lane);
            nms_step1c(i+3, b3, remv, cur, slot, owner, lane, cnt, done);
            if (done) break;
            nms_load1(i+7, b3, lane);
        }
    }
    for (int t = cnt + lane; t < KP; t += 32) g_keep1[t] = 0;
}

// ---------------- NMS scan 2: cached current-word ----------------
__device__ __forceinline__ void nms_step2c(int i, unsigned long long buf,
                                           unsigned long long &remv,
                                           unsigned long long &cur, int owner,
                                           int lane, int &cnt, bool &done){
    if (i < KP && !((cur >> (i & 63)) & 1ULL)){
        if (lane == 0 && cnt < KP) g_keep2[cnt] = g_idx2[i];
        cnt++;
        if (cnt >= KP){ done = true; return; }
        remv |= buf;
        cur |= __shfl_sync(FULLM, buf, owner);
    }
}
__global__ void k_scan2(){
    int lane = threadIdx.x;
    unsigned long long remv = 0;
    unsigned long long b0, b1, b2, b3;
    int cnt = 0;
    bool done = false;
    b0 = g_mask2[(size_t)0*NBW2 + lane];
    b1 = g_mask2[(size_t)1*NBW2 + lane];
    b2 = g_mask2[(size_t)2*NBW2 + lane];
    b3 = g_mask2[(size_t)3*NBW2 + lane];
    for (int g = 0; g < NBW2 && !done; g++){
        unsigned long long cur = __shfl_sync(FULLM, remv, g);
        for (int c = 0; c < 16 && !done; c++){
            int i = g*64 + c*4;
            nms_step2c(i+0, b0, remv, cur, g, lane, cnt, done);
            if (done) break;
            b0 = (i+4 < KP) ? g_mask2[(size_t)(i+4)*NBW2 + lane] : 0ULL;
            nms_step2c(i+1, b1, remv, cur, g, lane, cnt, done);
            if (done) break;
            b1 = (i+5 < KP) ? g_mask2[(size_t)(i+5)*NBW2 + lane] : 0ULL;
            nms_step2c(i+2, b2, remv, cur, g, lane, cnt, done);
            if (done) break;
            b2 = (i+6 < KP) ? g_mask2[(size_t)(i+6)*NBW2 + lane] : 0ULL;
            nms_step2c(i+3, b3, remv, cur, g, lane, cnt, done);
            if (done) break;
            b3 = (i+7 < KP) ? g_mask2[(size_t)(i+7)*NBW2 + lane] : 0ULL;
        }
    }
    if (lane == 0) g_nk2 = cnt;
    for (int t = cnt + lane; t < KP; t += 32) g_keep2[t] = 0;
}

// ---------------- proposals ----------------
__global__ void k_props(float* __restrict__ out){
    int i = blockIdx.x*blockDim.x + threadIdx.x;
    if (i < KP){
        int id = g_keep1[i];
        float4 b = ((const float4*)g_boxes)[id];
        out[O_PROPS + i*4+0] = b.x; out[O_PROPS + i*4+1] = b.y;
        out[O_PROPS + i*4+2] = b.z; out[O_PROPS + i*4+3] = b.w;
        ((float4*)g_prop4)[i] = b;
        g_nbox[i*4+0] = __fdiv_rn(b.y, 511.f);
        g_nbox[i*4+1] = __fdiv_rn(b.x, 511.f);
        g_nbox[i*4+2] = __fdiv_rn(b.w, 511.f);
        g_nbox[i*4+3] = __fdiv_rn(b.z, 511.f);
    }
}

// ---------------- crop + bilinear + 2x2 maxpool ----------------
__global__ void __launch_bounds__(256) k_crop(){
    int k = blockIdx.x;
    int warp = threadIdx.x >> 5, lane = threadIdx.x & 31;
    float y1 = g_nbox[k*4+0], x1 = g_nbox[k*4+1], y2 = g_nbox[k*4+2], x2 = g_nbox[k*4+3];
    float dy = __fsub_rn(y2, y1), dx = __fsub_rn(x2, x1);
    int c4 = lane*4;
    const float4* f = (const float4*)g_featT;
    for (int p = warp; p < 49; p += 8){
        int oi = p/7, oj = p%7;
        float4 acc = make_float4(-1e30f,-1e30f,-1e30f,-1e30f);
        #pragma unroll
        for (int di = 0; di < 2; di++){
            #pragma unroll
            for (int dj = 0; dj < 2; dj++){
                int ti = 2*oi+di, tj = 2*oj+dj;
                float ty = __fdiv_rn((float)ti, 13.f);
                float tx = __fdiv_rn((float)tj, 13.f);
                float ys = __fmul_rn(__fadd_rn(y1, __fmul_rn(ty, dy)), 31.f);
                float xs = __fmul_rn(__fadd_rn(x1, __fmul_rn(tx, dx)), 31.f);
                int y0 = min(max((int)floorf(ys), 0), 31);
                int y1i = min(y0+1, 31);
                int x0 = min(max((int)floorf(xs), 0), 31);
                int x1i = min(x0+1, 31);
                float wy = __fsub_rn(ys, (float)y0);
                float wx = __fsub_rn(xs, (float)x0);
                float omwx = __fsub_rn(1.f, wx), omwy = __fsub_rn(1.f, wy);
                float4 f00 = f[((y0*32+x0)*128 + c4) >> 2];
                float4 f01 = f[((y0*32+x1i)*128 + c4) >> 2];
                float4 f10 = f[((y1i*32+x0)*128 + c4) >> 2];
                float4 f11 = f[((y1i*32+x1i)*128 + c4) >> 2];
                #pragma unroll
                for (int e = 0; e < 4; e++){
                    float a00 = (&f00.x)[e], a01 = (&f01.x)[e];
                    float a10 = (&f10.x)[e], a11 = (&f11.x)[e];
                    float top = __fadd_rn(__fmul_rn(a00, omwx), __fmul_rn(a01, wx));
                    float bot = __fadd_rn(__fmul_rn(a10, omwx), __fmul_rn(a11, wx));
                    float val = __fadd_rn(__fmul_rn(top, omwy), __fmul_rn(bot, wy));
                    (&acc.x)[e] = fmaxf((&acc.x)[e], val);
                }
            }
        }
        ((float4*)g_flat)[((size_t)k*FK + p*128 + c4) >> 2] = acc;
    }
}

// ---------------- fp32 SIMT GEMM: 128x128 tile, 8x8 micro, double-buffered ----------------
#define GP 132
__global__ void __launch_bounds__(256) k_gemm(const float* __restrict__ A, const float* __restrict__ B,
                                              const float* __restrict__ bias, float* __restrict__ Cmat,
                                              int M, int N, int K){
    __shared__ float As[2][16][GP];
    __shared__ float Bs[2][16][GP];
    int tid = threadIdx.x;
    int tx = tid & 15, ty = tid >> 4;
    int mbase = blockIdx.y*128, nbase = blockIdx.x*128;
    float acc[8][8];
    #pragma unroll
    for (int r = 0; r < 8; r++)
        #pragma unroll
        for (int q = 0; q < 8; q++) acc[r][q] = 0.f;

    int r0 = tid >> 2,          c0 = (tid & 3) * 4;
    int r1 = (tid + 256) >> 2,  c1 = ((tid + 256) & 3) * 4;
    const float* Ap0 = A + (size_t)(mbase + r0)*K + c0;
    const float* Ap1 = A + (size_t)(mbase + r1)*K + c1;
    const float* Bp0 = B + (size_t)(nbase + r0)*K + c0;
    const float* Bp1 = B + (size_t)(nbase + r1)*K + c1;
    bool av0 = (mbase + r0) < M, av1 = (mbase + r1) < M;

    float4 a0 = av0 ? *(const float4*)Ap0 : make_float4(0,0,0,0);
    float4 a1 = av1 ? *(const float4*)Ap1 : make_float4(0,0,0,0);
    float4 b0 = *(const float4*)Bp0;
    float4 b1 = *(const float4*)Bp1;
    As[0][c0+0][r0]=a0.x; As[0][c0+1][r0]=a0.y; As[0][c0+2][r0]=a0.z; As[0][c0+3][r0]=a0.w;
    As[0][c1+0][r1]=a1.x; As[0][c1+1][r1]=a1.y; As[0][c1+2][r1]=a1.z; As[0][c1+3][r1]=a1.w;
    Bs[0][c0+0][r0]=b0.x; Bs[0][c0+1][r0]=b0.y; Bs[0][c0+2][r0]=b0.z; Bs[0][c0+3][r0]=b0.w;
    Bs[0][c1+0][r1]=b1.x; Bs[0][c1+1][r1]=b1.y; Bs[0][c1+2][r1]=b1.z; Bs[0][c1+3][r1]=b1.w;
    __syncthreads();

    int nIter = K / 16;
    for (int it = 0; it < nIter; it++){
        int buf = it & 1;
        float4 na0, na1, nb0, nb1;
        if (it + 1 < nIter){
            int koff = (it+1)*16;
            na0 = av0 ? *(const float4*)(Ap0 + koff) : make_float4(0,0,0,0);
            na1 = av1 ? *(const float4*)(Ap1 + koff) : make_float4(0,0,0,0);
            nb0 = *(const float4*)(Bp0 + koff);
            nb1 = *(const float4*)(Bp1 + koff);
        }
        #pragma unroll
        for (int kk = 0; kk < 16; kk++){
            float ar[8], br[8];
            *(float4*)(ar)   = *(const float4*)&As[buf][kk][ty*8];
            *(float4*)(ar+4) = *(const float4*)&As[buf][kk][ty*8+4];
            *(float4*)(br)   = *(const float4*)&Bs[buf][kk][tx*8];
            *(float4*)(br+4) = *(const float4*)&Bs[buf][kk][tx*8+4];
            #pragma unroll
            for (int r = 0; r < 8; r++)
                #pragma unroll
                for (int q = 0; q < 8; q++)
                    acc[r][q] = fmaf(ar[r], br[q], acc[r][q]);
        }
        if (it + 1 < nIter){
            int nb = buf ^ 1;
            __syncthreads();
            As[nb][c0+0][r0]=na0.x; As[nb][c0+1][r0]=na0.y; As[nb][c0+2][r0]=na0.z; As[nb][c0+3][r0]=na0.w;
            As[nb][c1+0][r1]=na1.x; As[nb][c1+1][r1]=na1.y; As[nb][c1+2][r1]=na1.z; As[nb][c1+3][r1]=na1.w;
            Bs[nb][c0+0][r0]=nb0.x; Bs[nb][c0+1][r0]=nb0.y; Bs[nb][c0+2][r0]=nb0.z; Bs[nb][c0+3][r0]=nb0.w;
            Bs[nb][c1+0][r1]=nb1.x; Bs[nb][c1+1][r1]=nb1.y; Bs[nb][c1+2][r1]=nb1.z; Bs[nb][c1+3][r1]=nb1.w;
            __syncthreads();
        }
    }
    #pragma unroll
    for (int r = 0; r < 8; r++){
        int row = mbase + ty*8 + r;
        if (row < M){
            #pragma unroll
            for (int q = 0; q < 8; q++){
                int col = nbase + tx*8 + q;
                Cmat[(size_t)row*N + col] = fmaxf(__fadd_rn(acc[r][q], bias[col]), 0.f);
            }
        }
    }
}

// ---------------- RCNN heads + decode2 (fp64 dots — cheap, keep proven path) ----------------
__global__ void __launch_bounds__(192) k_heads(const float* __restrict__ cw, const float* __restrict__ cb,
                                               const float* __restrict__ rw, const float* __restrict__ rb,
                                               float* __restrict__ out){
    __shared__ float sd[6];
    int k = blockIdx.x;
    int warp = threadIdx.x >> 5, lane = threadIdx.x & 31;
    const float4* h4 = (const float4*)(g_h2 + (size_t)k*1024);
    const float4* w4 = (const float4*)((warp < 2) ? (cw + warp*1024) : (rw + (warp-2)*1024));
    double acc = 0.0;
    #pragma unroll
    for (int q = 0; q < 8; q++){
        float4 a = h4[lane + q*32], b = w4[lane + q*32];
        acc = fma((double)a.x, (double)b.x, acc);
        acc = fma((double)a.y, (double)b.y, acc);
        acc = fma((double)a.z, (double)b.z, acc);
        acc = fma((double)a.w, (double)b.w, acc);
    }
    #pragma unroll
    for (int o = 16; o; o >>= 1) acc += __shfl_xor_sync(FULLM, acc, o);
    if (lane == 0) sd[warp] = __fadd_rn((float)acc, (warp < 2) ? cb[warp] : rb[warp-2]);
    __syncthreads();
    if (threadIdx.x == 0){
        float l0 = sd[0], l1 = sd[1];
        out[O_RCL + k*2+0] = l0; out[O_RCL + k*2+1] = l1;
        float d0 = sd[2], d1 = sd[3], d2 = sd[4], d3 = sd[5];
        out[O_RCD + k*4+0]=d0; out[O_RCD + k*4+1]=d1;
        out[O_RCD + k*4+2]=d2; out[O_RCD + k*4+3]=d3;
        float score = softmax1(l0, l1);
        float4 pr = ((const float4*)g_prop4)[k];
        float w = __fadd_rn(__fsub_rn(pr.z, pr.x), 1.f);
        float h = __fadd_rn(__fsub_rn(pr.w, pr.y), 1.f);
        float ccx = __fadd_rn(pr.x, __fmul_rn(0.5f, w));
        float ccy = __fadd_rn(pr.y, __fmul_rn(0.5f, h));
        float pcx = __fadd_rn(__fmul_rn(d0, w), ccx);
        float pcy = __fadd_rn(__fmul_rn(d1, h), ccy);
        float pw = __fmul_rn(exp_strict(d2), w);
        float ph = __fmul_rn(exp_strict(d3), h);
        float hw = __fmul_rn(0.5f, pw), hh = __fmul_rn(0.5f, ph);
        float4 dt;
        dt.x = fminf(fmaxf(__fsub_rn(pcx, hw), 0.f), 511.f);
        dt.y = fminf(fmaxf(__fsub_rn(pcy, hh), 0.f), 511.f);
        dt.z = fminf(fmaxf(__fadd_rn(pcx, hw), 0.f), 511.f);
        dt.w = fminf(fmaxf(__fadd_rn(pcy, hh), 0.f), 511.f);
        ((float4*)g_dets)[k] = dt;
        g_rsc[k] = score;
        g_key2[k] = score;
        g_idx2[k] = k;
    }
}

// ---------------- final outputs ----------------
__global__ void k_final(float* __restrict__ out){
    int i = blockIdx.x*blockDim.x + threadIdx.x;
    if (i < KP){
        float m = (i < g_nk2) ? 1.f : 0.f;
        int id = g_keep2[i];
        float4 d = ((const float4*)g_dets)[id];
        out[O_DETS + i*4+0] = d.x*m; out[O_DETS + i*4+1] = d.y*m;
        out[O_DETS + i*4+2] = d.z*m; out[O_DETS + i*4+3] = d.w*m;
        out[O_SC + i] = g_rsc[id]*m;
    }
}

// ---------------- launch ----------------
extern "C" void kernel_launch(void* const* d_in, const int* in_sizes, int n_in,
                              void* d_out, int out_size){
    const float* x        = (const float*)d_in[0];
    const float* bb_w     = (const float*)d_in[1];
    const float* bb_b     = (const float*)d_in[2];
    const float* rpn_w    = (const float*)d_in[3];
    const float* rpn_b    = (const float*)d_in[4];
    const float* rpn_cls_w= (const float*)d_in[5];
    const float* rpn_cls_b= (const float*)d_in[6];
    const float* rpn_reg_w= (const float*)d_in[7];
    const float* rpn_reg_b= (const float*)d_in[8];
    const float* fc1_w    = (const float*)d_in[9];
    const float* fc1_b    = (const float*)d_in[10];
    const float* fc2_w    = (const float*)d_in[11];
    const float* fc2_b    = (const float*)d_in[12];
    const float* cls_w    = (const float*)d_in[13];
    const float* cls_b    = (const float*)d_in[14];
    const float* reg_w    = (const float*)d_in[15];
    const float* reg_b    = (const float*)d_in[16];
    float* out = (float*)d_out;

    float *p_key1, *p_key2, *p_sbox1, *p_sdet, *p_flat, *p_fc1wP, *p_h1, *p_h2;
    int *p_idx1, *p_idx2;
    unsigned long long *p_mask1, *p_mask2;
    cudaGetSymbolAddress((void**)&p_key1,  g_key1);
    cudaGetSymbolAddress((void**)&p_idx1,  g_idx1);
    cudaGetSymbolAddress((void**)&p_key2,  g_key2);
    cudaGetSymbolAddress((void**)&p_idx2,  g_idx2);
    cudaGetSymbolAddress((void**)&p_sbox1, g_sbox1);
    cudaGetSymbolAddress((void**)&p_sdet,  g_sdet);
    cudaGetSymbolAddress((void**)&p_mask1, g_mask1);
    cudaGetSymbolAddress((void**)&p_mask2, g_mask2);
    cudaGetSymbolAddress((void**)&p_flat,  g_flat);
    cudaGetSymbolAddress((void**)&p_fc1wP, g_fc1wP);
    cudaGetSymbolAddress((void**)&p_h1,    g_h1);
    cudaGetSymbolAddress((void**)&p_h2,    g_h2);

    k_transpose<<<(768*128+255)/256, 256>>>(bb_w, 768, 0);
    k_transpose<<<(1152*128+255)/256, 256>>>(rpn_w, 1152, 1);
    k_tfc1<<<1024, 256>>>(fc1_w);
    k_init<<<32, 256>>>();

    k_conv1<<<256, 128>>>(x, bb_b);
    k_conv2<<<256, 128>>>(rpn_b);
    k_rpn<<<1024, 64>>>(rpn_cls_w, rpn_cls_b, rpn_reg_w, rpn_reg_b, out);

    // hybrid bitonic sort over 16384 (desc score, tie idx asc)
    k_sort_local<<<8, 1024>>>(p_key1, p_idx1);
    for (int kk = 4096; kk <= NPAD1; kk <<= 1){
        for (int j = kk >> 1; j >= 2048; j >>= 1)
            k_sort_global<<<NPAD1/256, 256>>>(p_key1, p_idx1, kk, j, NPAD1);
        k_merge_local<<<8, 1024>>>(p_key1, p_idx1, kk);
    }

    k_gather1<<<(NANCH+255)/256, 256>>>();
    {
        dim3 g(NBW1, NBW1);
        k_mask<<<g, 64>>>(p_sbox1, NANCH, NBW1, p_mask1, 0.5f);
    }
    k_scan1<<<1, 32>>>();
    k_props<<<(KP+255)/256, 256>>>(out);
    k_crop<<<KP, 256>>>();

    {
        dim3 g1(8, 16);
        k_gemm<<<g1, 256>>>(p_flat, p_fc1wP, fc1_b, p_h1, KP, 1024, FK);
        k_gemm<<<g1, 256>>>(p_h1, fc2_w, fc2_b, p_h2, KP, 1024, 1024);
    }
    k_heads<<<KP, 192>>>(cls_w, cls_b, reg_w, reg_b, out);

    k_sort_local<<<1, 1024>>>(p_key2, p_idx2);

    k_gather2<<<(KP+255)/256, 256>>>();
    {
        dim3 g(NBW2, NBW2);
        k_mask<<<g, 64>>>(p_sdet, KP, NBW2, p_mask2, 0.3f);
    }
    k_scan2<<<1, 32>>>();
    k_final<<<(KP+255)/256, 256>>>(out);
}

// round 15
// speedup vs baseline: 1.9425x; 1.0065x over previous
#include <cuda_runtime.h>
#include <math.h>

#define NANCH 9216
#define NPAD1 16384
#define NBW1  144
#define KP    2000
#define NPAD2 2048
#define NBW2  32
#define FK    6272
#define FULLM 0xffffffffu

// output offsets (floats)
#define O_RPNL  0
#define O_RPND  18432
#define O_PROPS 55296
#define O_ANCH  63296
#define O_RCL   100160
#define O_RCD   104160
#define O_DETS  112160
#define O_SC    120160

// ---------------- device scratch ----------------
__device__ __align__(16) float g_featT[32*32*128];
__device__ __align__(16) float g_hT[32*32*128];
__device__ __align__(16) float g_bbT[768*128];
__device__ __align__(16) float g_rwT[1152*128];
__device__ __align__(16) float g_fc1wP[1024*FK];
__device__ __align__(16) float g_boxes[NANCH*4];
__device__ float g_key1[NPAD1];
__device__ int   g_idx1[NPAD1];
__device__ __align__(16) float g_sbox1[NANCH*4];
__device__ unsigned long long g_mask1[(size_t)NANCH*NBW1];
__device__ int   g_keep1[KP];
__device__ __align__(16) float g_prop4[KP*4];
__device__ __align__(16) float g_nbox[KP*4];
__device__ __align__(16) float g_flat[(size_t)KP*FK];
__device__ __align__(16) float g_h1[KP*1024];
__device__ __align__(16) float g_h2[KP*1024];
__device__ float g_rsc[KP];
__device__ __align__(16) float g_dets[KP*4];
__device__ float g_key2[NPAD2];
__device__ int   g_idx2[NPAD2];
__device__ __align__(16) float g_sdet[KP*4];
__device__ unsigned long long g_mask2[(size_t)KP*NBW2];
__device__ int   g_keep2[KP];
__device__ int   g_nk2;

// fast-math-immune, correctly-rounded fp32 exp
__device__ __forceinline__ float exp_strict(float x){
    return (float)exp((double)x);
}

// exact mirror of jax.nn.softmax([l0,l1])[1] in fp32
__device__ __forceinline__ float softmax1(float l0, float l1){
    float m = fmaxf(l0, l1);
    float e0 = exp_strict(__fsub_rn(l0, m));
    float e1 = exp_strict(__fsub_rn(l1, m));
    return __fdiv_rn(e1, __fadd_rn(e0, e1));
}

// Compensated (double-float) accumulate: s+c += a*w with ~1e-9 relative error.
#define DF_ACC(a, w, s, c) { \
    float _p = __fmul_rn((a), (w)); \
    float _e = __fmaf_rn((a), (w), -_p); \
    float _t = __fadd_rn((s), _p); \
    float _z = __fsub_rn(_t, (s)); \
    float _e2 = __fadd_rn(__fsub_rn(_p, _z), __fsub_rn((s), __fsub_rn(_t, _z))); \
    (s) = _t; \
    (c) = __fadd_rn((c), __fadd_rn(_e, _e2)); \
}

// ---------------- weight permutes ----------------
__global__ void k_transpose(const float* __restrict__ src, int K, int which){
    float* dst = which ? g_rwT : g_bbT;
    int t = blockIdx.x*blockDim.x + threadIdx.x;
    if (t < K*128){
        int i = t >> 7, c = t & 127;
        dst[t] = src[c*K + i];
    }
}

__global__ void __launch_bounds__(256) k_tfc1(const float* __restrict__ w){
    __shared__ float s[FK];
    int h = blockIdx.x;
    const float* src = w + (size_t)h*FK;
    for (int t = threadIdx.x; t < FK; t += 256) s[t] = src[t];
    __syncthreads();
    float* dst = g_fc1wP + (size_t)h*FK;
    for (int t = threadIdx.x; t < FK; t += 256){
        int p = t >> 7, c = t & 127;
        dst[t] = s[c*49 + p];
    }
}

__global__ void k_init(){
    int t = blockIdx.x*blockDim.x + threadIdx.x;
    if (t < NPAD1 - NANCH){ g_key1[NANCH+t] = -1.f; g_idx1[NANCH+t] = 0x7fffffff; }
    if (t < NPAD2 - KP)   { g_key2[KP+t]    = -1.f; g_idx2[KP+t]    = 0x7fffffff; }
}

// ---------------- conv1: 3->128, 16x16 stride16 VALID, relu (compensated fp32) ----------------
__global__ void __launch_bounds__(128) k_conv1(const float* __restrict__ x, const float* __restrict__ bias){
    __shared__ float sp[4*768];
    int gy  = blockIdx.x >> 3;
    int gx0 = (blockIdx.x & 7) * 4;
    int tid = threadIdx.x;
    for (int e = tid; e < 3072; e += 128){
        int spx = e / 768, i = e % 768;
        int ci = i >> 8, rr = i & 255, ky = rr >> 4, kx = rr & 15;
        sp[e] = x[ci*(512*512) + (gy*16+ky)*512 + (gx0+spx)*16 + kx];
    }
    __syncthreads();
    float s0=0.f,c0=0.f, s1=0.f,c1=0.f, s2=0.f,c2=0.f, s3=0.f,c3=0.f;
    for (int i = 0; i < 768; i++){
        float w = g_bbT[i*128 + tid];
        DF_ACC(sp[i],      w, s0, c0);
        DF_ACC(sp[768+i],  w, s1, c1);
        DF_ACC(sp[1536+i], w, s2, c2);
        DF_ACC(sp[2304+i], w, s3, c3);
    }
    float b = bias[tid];
    int base = (gy*32 + gx0)*128 + tid;
    g_featT[base      ] = fmaxf(__fadd_rn(__fadd_rn(s0, c0), b), 0.f);
    g_featT[base + 128] = fmaxf(__fadd_rn(__fadd_rn(s1, c1), b), 0.f);
    g_featT[base + 256] = fmaxf(__fadd_rn(__fadd_rn(s2, c2), b), 0.f);
    g_featT[base + 384] = fmaxf(__fadd_rn(__fadd_rn(s3, c3), b), 0.f);
}

// ---------------- conv2: 3x3 SAME 128->128, relu (compensated fp32) ----------------
__global__ void __launch_bounds__(128) k_conv2(const float* __restrict__ bias){
    __shared__ float sp[18*128];
    int gy  = blockIdx.x >> 3;
    int gx0 = (blockIdx.x & 7) * 4;
    int tid = threadIdx.x;
    for (int e = tid; e < 18*128; e += 128){
        int pix = e >> 7, ci = e & 127;
        int ky = pix / 6, sx = pix % 6;
        int iy = gy + ky - 1, ix = gx0 + sx - 1;
        float v = 0.f;
        if (iy >= 0 && iy < 32 && ix >= 0 && ix < 32) v = g_featT[(iy*32+ix)*128 + ci];
        sp[e] = v;
    }
    __syncthreads();
    float s0=0.f,c0=0.f, s1=0.f,c1=0.f, s2=0.f,c2=0.f, s3=0.f,c3=0.f;
    int i = 0;
    for (int ci = 0; ci < 128; ci++){
        #pragma unroll
        for (int ky = 0; ky < 3; ky++){
            #pragma unroll
            for (int kx = 0; kx < 3; kx++){
                float w = g_rwT[i*128 + tid];
                int base = (ky*6+kx)*128 + ci;
                DF_ACC(sp[base      ], w, s0, c0);
                DF_ACC(sp[base + 128], w, s1, c1);
                DF_ACC(sp[base + 256], w, s2, c2);
                DF_ACC(sp[base + 384], w, s3, c3);
                i++;
            }
        }
    }
    float b = bias[tid];
    int ob = (gy*32+gx0)*128 + tid;
    g_hT[ob      ] = fmaxf(__fadd_rn(__fadd_rn(s0, c0), b), 0.f);
    g_hT[ob + 128] = fmaxf(__fadd_rn(__fadd_rn(s1, c1), b), 0.f);
    g_hT[ob + 256] = fmaxf(__fadd_rn(__fadd_rn(s2, c2), b), 0.f);
    g_hT[ob + 384] = fmaxf(__fadd_rn(__fadd_rn(s3, c3), b), 0.f);
}

// ---------------- RPN heads + softmax + anchors + decode + clip ----------------
__global__ void __launch_bounds__(64) k_rpn(const float* __restrict__ cw, const float* __restrict__ cb,
                                            const float* __restrict__ rw, const float* __restrict__ rb,
                                            float* __restrict__ out){
    __shared__ float sh[128];
    __shared__ float sd[54];
    int pix = blockIdx.x;
    int tid = threadIdx.x;
    sh[tid]      = g_hT[pix*128 + tid];
    sh[tid + 64] = g_hT[pix*128 + tid + 64];
    __syncthreads();
    if (tid < 54){
        const float* wrow = (tid < 18) ? (cw + tid*128) : (rw + (tid-18)*128);
        float bb = (tid < 18) ? cb[tid] : rb[tid-18];
        float s = 0.f, c = 0.f;
        for (int cc = 0; cc < 128; cc++){
            DF_ACC(sh[cc], wrow[cc], s, c);
        }
        sd[tid] = __fadd_rn(__fadd_rn(s, c), bb);
    }
    __syncthreads();
    if (tid < 9){
        int a = tid;
        int y = pix >> 5, x = pix & 31;
        int n = pix*9 + a;
        float l0 = sd[2*a], l1 = sd[2*a+1];
        out[O_RPNL + n*2+0] = l0; out[O_RPNL + n*2+1] = l1;
        float d0 = sd[18+4*a+0], d1 = sd[18+4*a+1], d2 = sd[18+4*a+2], d3 = sd[18+4*a+3];
        out[O_RPND + n*4+0]=d0; out[O_RPND + n*4+1]=d1;
        out[O_RPND + n*4+2]=d2; out[O_RPND + n*4+3]=d3;
        const float scv[3] = {32.f, 64.f, 128.f};
        const float rv[3]  = {0.5f, 1.f, 2.f};
        int si = a/3, ri = a%3;
        float sr = __fsqrt_rn(rv[ri]);
        float ws = __fdiv_rn(scv[si], sr);
        float hs = __fmul_rn(scv[si], sr);
        float cx = __fmul_rn(__fadd_rn((float)x, 0.5f), 16.f);
        float cy = __fmul_rn(__fadd_rn((float)y, 0.5f), 16.f);
        float W2 = __fmul_rn(ws, 0.5f);
        float H2 = __fmul_rn(hs, 0.5f);
        float ax1 = __fsub_rn(cx, W2), ay1 = __fsub_rn(cy, H2);
        float ax2 = __fadd_rn(cx, W2), ay2 = __fadd_rn(cy, H2);
        out[O_ANCH + n*4+0]=ax1; out[O_ANCH + n*4+1]=ay1;
        out[O_ANCH + n*4+2]=ax2; out[O_ANCH + n*4+3]=ay2;
        float w = __fadd_rn(__fsub_rn(ax2, ax1), 1.f);
        float h = __fadd_rn(__fsub_rn(ay2, ay1), 1.f);
        float ccx = __fadd_rn(ax1, __fmul_rn(0.5f, w));
        float ccy = __fadd_rn(ay1, __fmul_rn(0.5f, h));
        float pcx = __fadd_rn(__fmul_rn(d0, w), ccx);
        float pcy = __fadd_rn(__fmul_rn(d1, h), ccy);
        float pw = __fmul_rn(exp_strict(d2), w);
        float ph = __fmul_rn(exp_strict(d3), h);
        float hw = __fmul_rn(0.5f, pw), hh = __fmul_rn(0.5f, ph);
        g_boxes[n*4+0] = fminf(fmaxf(__fsub_rn(pcx, hw), 0.f), 511.f);
        g_boxes[n*4+1] = fminf(fmaxf(__fsub_rn(pcy, hh), 0.f), 511.f);
        g_boxes[n*4+2] = fminf(fmaxf(__fadd_rn(pcx, hw), 0.f), 511.f);
        g_boxes[n*4+3] = fminf(fmaxf(__fadd_rn(pcy, hh), 0.f), 511.f);
        g_key1[n] = softmax1(l0, l1);
        g_idx1[n] = n;
    }
}

// ---------------- hybrid bitonic sort (desc score, tie idx asc) ----------------
__device__ __forceinline__ bool cmp_before(float ka, int ia, float kb, int ib){
    return (ka > kb) || (ka == kb && ia < ib);
}

__global__ void __launch_bounds__(1024) k_sort_local(float* __restrict__ key, int* __restrict__ idx){
    __shared__ float sk[2048];
    __shared__ int   si[2048];
    int base = blockIdx.x * 2048;
    for (int t = threadIdx.x; t < 2048; t += 1024){ sk[t] = key[base+t]; si[t] = idx[base+t]; }
    __syncthreads();
    for (int kk = 2; kk <= 2048; kk <<= 1){
        for (int j = kk >> 1; j > 0; j >>= 1){
            for (int t = threadIdx.x; t < 2048; t += 1024){
                int p = t ^ j;
                if (p > t){
                    bool up = (((base + t) & kk) == 0);
                    float ka = sk[t], kb = sk[p];
                    int ia = si[t], ib = si[p];
                    bool sw = up ? cmp_before(kb, ib, ka, ia) : cmp_before(ka, ia, kb, ib);
                    if (sw){ sk[t]=kb; si[t]=ib; sk[p]=ka; si[p]=ia; }
                }
            }
            __syncthreads();
        }
    }
    for (int t = threadIdx.x; t < 2048; t += 1024){ key[base+t] = sk[t]; idx[base+t] = si[t]; }
}

__global__ void __launch_bounds__(256) k_sort_global(float* __restrict__ key, int* __restrict__ idx,
                                                     int kk, int j, int npad){
    int i = blockIdx.x*256 + threadIdx.x;
    int p = i ^ j;
    if (i < npad && p > i && p < npad){
        bool up = ((i & kk) == 0);
        float ka = key[i], kb = key[p];
        int ia = idx[i], ib = idx[p];
        bool sw = up ? cmp_before(kb, ib, ka, ia) : cmp_before(ka, ia, kb, ib);
        if (sw){ key[i]=kb; idx[i]=ib; key[p]=ka; idx[p]=ia; }
    }
}

__global__ void __launch_bounds__(1024) k_merge_local(float* __restrict__ key, int* __restrict__ idx, int kk){
    __shared__ float sk[2048];
    __shared__ int   si[2048];
    int base = blockIdx.x * 2048;
    for (int t = threadIdx.x; t < 2048; t += 1024){ sk[t] = key[base+t]; si[t] = idx[base+t]; }
    __syncthreads();
    for (int j = 1024; j > 0; j >>= 1){
        for (int t = threadIdx.x; t < 2048; t += 1024){
            int p = t ^ j;
            if (p > t){
                bool up = (((base + t) & kk) == 0);
                float ka = sk[t], kb = sk[p];
                int ia = si[t], ib = si[p];
                bool sw = up ? cmp_before(kb, ib, ka, ia) : cmp_before(ka, ia, kb, ib);
                if (sw){ sk[t]=kb; si[t]=ib; sk[p]=ka; si[p]=ia; }
            }
        }
        __syncthreads();
    }
    for (int t = threadIdx.x; t < 2048; t += 1024){ key[base+t] = sk[t]; idx[base+t] = si[t]; }
}

// ---------------- gathers ----------------
__global__ void k_gather1(){
    int i = blockIdx.x*blockDim.x + threadIdx.x;
    if (i < NANCH){
        int id = g_idx1[i];
        ((float4*)g_sbox1)[i] = ((const float4*)g_boxes)[id];
    }
}

__global__ void k_gather2(){
    int i = blockIdx.x*blockDim.x + threadIdx.x;
    if (i < KP){
        int id = g_idx2[i];
        ((float4*)g_sdet)[i] = ((const float4*)g_dets)[id];
    }
}

// ---------------- NMS mask build (triangle skip + div skip) ----------------
__global__ void __launch_bounds__(64) k_mask(const float* __restrict__ sbox, int n, int nbw,
                                             unsigned long long* __restrict__ mask, float thr){
    int ib = blockIdx.y, jb = blockIdx.x;
    if (jb < ib) return;
    __shared__ float4 cb[64];
    __shared__ float  ca[64];
    int cj = jb*64 + threadIdx.x;
    if (cj < n){
        float4 b = ((const float4*)sbox)[cj];
        cb[threadIdx.x] = b;
        ca[threadIdx.x] = __fmul_rn(__fadd_rn(__fsub_rn(b.z,b.x),1.f), __fadd_rn(__fsub_rn(b.w,b.y),1.f));
    } else {
        cb[threadIdx.x] = make_float4(0,0,0,0);
        ca[threadIdx.x] = 1.f;
    }
    __syncthreads();
    int r = ib*64 + threadIdx.x;
    if (r >= n) return;
    float4 rb = ((const float4*)sbox)[r];
    float ra = __fmul_rn(__fadd_rn(__fsub_rn(rb.z,rb.x),1.f), __fadd_rn(__fsub_rn(rb.w,rb.y),1.f));
    unsigned long long m = 0;
    if (jb*64 + 63 > r){
        #pragma unroll 4
        for (int b = 0; b < 64; b++){
            int j = jb*64 + b;
            if (j > r && j < n){
                float4 o = cb[b];
                float xx1 = fmaxf(rb.x, o.x), yy1 = fmaxf(rb.y, o.y);
                float xx2 = fminf(rb.z, o.z), yy2 = fminf(rb.w, o.w);
                float iw = fmaxf(__fadd_rn(__fsub_rn(xx2,xx1),1.f), 0.f);
                float ih = fmaxf(__fadd_rn(__fsub_rn(yy2,yy1),1.f), 0.f);
                float inter = __fmul_rn(iw, ih);
                if (inter > 0.f){
                    float iou = __fdiv_rn(inter, __fsub_rn(__fadd_rn(ra, ca[b]), inter));
                    if (iou > thr) m |= (1ULL << b);
                }
            }
        }
    }
    mask[(size_t)r*nbw + jb] = m;
}

// ---------------- NMS scan 1: cached current-word, shfl only on keep ----------------
__device__ __forceinline__ void nms_load1(int i, unsigned long long (&buf)[5], int lane){
    #pragma unroll
    for (int q = 0; q < 5; q++){
        int wq = q*32 + lane;
        buf[q] = (i < NANCH && wq < NBW1) ? g_mask1[(size_t)i*NBW1 + wq] : 0ULL;
    }
}
__device__ __forceinline__ unsigned long long sel5(const unsigned long long (&v)[5], int slot){
    return slot==0?v[0]:slot==1?v[1]:slot==2?v[2]:slot==3?v[3]:v[4];
}
__device__ __forceinline__ void nms_step1c(int i, unsigned long long (&buf)[5],
                                           unsigned long long (&remv)[5],
                                           unsigned long long &cur, int slot, int owner,
                                           int lane, int &cnt, bool &done){
    if (!((cur >> (i & 63)) & 1ULL)){
        if (lane == 0 && cnt < KP) g_keep1[cnt] = g_idx1[i];
        cnt++;
        if (cnt >= KP){ done = true; return; }
        #pragma unroll
        for (int q = 0; q < 5; q++) remv[q] |= buf[q];
        unsigned long long dw = sel5(buf, slot);
        cur |= __shfl_sync(FULLM, dw, owner);
    }
}
__global__ void k_scan1(){
    int lane = threadIdx.x;
    unsigned long long remv[5] = {0,0,0,0,0};
    unsigned long long b0[5], b1[5], b2[5], b3[5];
    int cnt = 0;
    bool done = false;
    nms_load1(0,b0,lane); nms_load1(1,b1,lane); nms_load1(2,b2,lane); nms_load1(3,b3,lane);
    for (int g = 0; g < NANCH/64 && !done; g++){
        int slot = g >> 5, owner = g & 31;
        unsigned long long cur = __shfl_sync(FULLM, sel5(remv, slot), owner);
        for (int c = 0; c < 16 && !done; c++){
            int i = g*64 + c*4;
            nms_step1c(i+0, b0, remv, cur, slot, owner, lane, cnt, done);
            if (done) break;
            nms_load1(i+4, b0, lane);
            nms_step1c(i+1, b1, remv, cur, slot, owner, lane, cnt, done);
            if (done) break;
            nms_load1(i+5, b1, lane);
            nms_step1c(i+2, b2, remv, cur, slot, owner, lane, cnt, done);
            if (done) break;
            nms_load1(i+6, b2, lane);
            nms_step1c(i+3, b3, remv, cur, slot, owner, lane, cnt, done);
            if (done) break;
            nms_load1(i+7, b3, lane);
        }
    }
    for (int t = cnt + lane; t < KP; t += 32) g_keep1[t] = 0;
}

// ---------------- NMS scan 2: cached current-word ----------------
__device__ __forceinline__ void nms_step2c(int i, unsigned long long buf,
                                           unsigned long long &remv,
                                           unsigned long long &cur, int owner,
                                           int lane, int &cnt, bool &done){
    if (i < KP && !((cur >> (i & 63)) & 1ULL)){
        if (lane == 0 && cnt < KP) g_keep2[cnt] = g_idx2[i];
        cnt++;
        if (cnt >= KP){ done = true; return; }
        remv |= buf;
        cur |= __shfl_sync(FULLM, buf, owner);
    }
}
__global__ void k_scan2(){
    int lane = threadIdx.x;
    unsigned long long remv = 0;
    unsigned long long b0, b1, b2, b3;
    int cnt = 0;
    bool done = false;
    b0 = g_mask2[(size_t)0*NBW2 + lane];
    b1 = g_mask2[(size_t)1*NBW2 + lane];
    b2 = g_mask2[(size_t)2*NBW2 + lane];
    b3 = g_mask2[(size_t)3*NBW2 + lane];
    for (int g = 0; g < NBW2 && !done; g++){
        unsigned long long cur = __shfl_sync(FULLM, remv, g);
        for (int c = 0; c < 16 && !done; c++){
            int i = g*64 + c*4;
            nms_step2c(i+0, b0, remv, cur, g, lane, cnt, done);
            if (done) break;
            b0 = (i+4 < KP) ? g_mask2[(size_t)(i+4)*NBW2 + lane] : 0ULL;
            nms_step2c(i+1, b1, remv, cur, g, lane, cnt, done);
            if (done) break;
            b1 = (i+5 < KP) ? g_mask2[(size_t)(i+5)*NBW2 + lane] : 0ULL;
            nms_step2c(i+2, b2, remv, cur, g, lane, cnt, done);
            if (done) break;
            b2 = (i+6 < KP) ? g_mask2[(size_t)(i+6)*NBW2 + lane] : 0ULL;
            nms_step2c(i+3, b3, remv, cur, g, lane, cnt, done);
            if (done) break;
            b3 = (i+7 < KP) ? g_mask2[(size_t)(i+7)*NBW2 + lane] : 0ULL;
        }
    }
    if (lane == 0) g_nk2 = cnt;
    for (int t = cnt + lane; t < KP; t += 32) g_keep2[t] = 0;
}

// ---------------- proposals ----------------
__global__ void k_props(float* __restrict__ out){
    int i = blockIdx.x*blockDim.x + threadIdx.x;
    if (i < KP){
        int id = g_keep1[i];
        float4 b = ((const float4*)g_boxes)[id];
        out[O_PROPS + i*4+0] = b.x; out[O_PROPS + i*4+1] = b.y;
        out[O_PROPS + i*4+2] = b.z; out[O_PROPS + i*4+3] = b.w;
        ((float4*)g_prop4)[i] = b;
        g_nbox[i*4+0] = __fdiv_rn(b.y, 511.f);
        g_nbox[i*4+1] = __fdiv_rn(b.x, 511.f);
        g_nbox[i*4+2] = __fdiv_rn(b.w, 511.f);
        g_nbox[i*4+3] = __fdiv_rn(b.z, 511.f);
    }
}

// ---------------- crop + bilinear + 2x2 maxpool ----------------
__global__ void __launch_bounds__(256) k_crop(){
    int k = blockIdx.x;
    int warp = threadIdx.x >> 5, lane = threadIdx.x & 31;
    float y1 = g_nbox[k*4+0], x1 = g_nbox[k*4+1], y2 = g_nbox[k*4+2], x2 = g_nbox[k*4+3];
    float dy = __fsub_rn(y2, y1), dx = __fsub_rn(x2, x1);
    int c4 = lane*4;
    const float4* f = (const float4*)g_featT;
    for (int p = warp; p < 49; p += 8){
        int oi = p/7, oj = p%7;
        float4 acc = make_float4(-1e30f,-1e30f,-1e30f,-1e30f);
        #pragma unroll
        for (int di = 0; di < 2; di++){
            #pragma unroll
            for (int dj = 0; dj < 2; dj++){
                int ti = 2*oi+di, tj = 2*oj+dj;
                float ty = __fdiv_rn((float)ti, 13.f);
                float tx = __fdiv_rn((float)tj, 13.f);
                float ys = __fmul_rn(__fadd_rn(y1, __fmul_rn(ty, dy)), 31.f);
                float xs = __fmul_rn(__fadd_rn(x1, __fmul_rn(tx, dx)), 31.f);
                int y0 = min(max((int)floorf(ys), 0), 31);
                int y1i = min(y0+1, 31);
                int x0 = min(max((int)floorf(xs), 0), 31);
                int x1i = min(x0+1, 31);
                float wy = __fsub_rn(ys, (float)y0);
                float wx = __fsub_rn(xs, (float)x0);
                float omwx = __fsub_rn(1.f, wx), omwy = __fsub_rn(1.f, wy);
                float4 f00 = f[((y0*32+x0)*128 + c4) >> 2];
                float4 f01 = f[((y0*32+x1i)*128 + c4) >> 2];
                float4 f10 = f[((y1i*32+x0)*128 + c4) >> 2];
                float4 f11 = f[((y1i*32+x1i)*128 + c4) >> 2];
                #pragma unroll
                for (int e = 0; e < 4; e++){
                    float a00 = (&f00.x)[e], a01 = (&f01.x)[e];
                    float a10 = (&f10.x)[e], a11 = (&f11.x)[e];
                    float top = __fadd_rn(__fmul_rn(a00, omwx), __fmul_rn(a01, wx));
                    float bot = __fadd_rn(__fmul_rn(a10, omwx), __fmul_rn(a11, wx));
                    float val = __fadd_rn(__fmul_rn(top, omwy), __fmul_rn(bot, wy));
                    (&acc.x)[e] = fmaxf((&acc.x)[e], val);
                }
            }
        }
        ((float4*)g_flat)[((size_t)k*FK + p*128 + c4) >> 2] = acc;
    }
}

// ---------------- fp32 SIMT GEMM: 128x128 tile, 512 threads, 8x4 micro, double-buffered ----------------
// Per-output k-accumulation order identical to prior version (sequential single
// accumulator) -> h1/h2 bitwise identical. 16 warps/SM hides LDS/sync latency.
#define GP 132
__global__ void __launch_bounds__(512) k_gemm(const float* __restrict__ A, const float* __restrict__ B,
                                              const float* __restrict__ bias, float* __restrict__ Cmat,
                                              int M, int N, int K){
    __shared__ float As[2][16][GP];
    __shared__ float Bs[2][16][GP];
    int tid = threadIdx.x;
    int tx = tid & 31, ty = tid >> 5;     // ty warp-uniform -> A-fragment broadcast
    int mbase = blockIdx.y*128, nbase = blockIdx.x*128;
    float acc[8][4];
    #pragma unroll
    for (int r = 0; r < 8; r++)
        #pragma unroll
        for (int q = 0; q < 4; q++) acc[r][q] = 0.f;

    // tile load: 512 float4 per matrix, one per thread
    int r0 = tid >> 2, c0 = (tid & 3) * 4;
    const float* Ap0 = A + (size_t)(mbase + r0)*K + c0;
    const float* Bp0 = B + (size_t)(nbase + r0)*K + c0;
    bool av0 = (mbase + r0) < M;

    float4 a0 = av0 ? *(const float4*)Ap0 : make_float4(0,0,0,0);
    float4 b0 = *(const float4*)Bp0;
    As[0][c0+0][r0]=a0.x; As[0][c0+1][r0]=a0.y; As[0][c0+2][r0]=a0.z; As[0][c0+3][r0]=a0.w;
    Bs[0][c0+0][r0]=b0.x; Bs[0][c0+1][r0]=b0.y; Bs[0][c0+2][r0]=b0.z; Bs[0][c0+3][r0]=b0.w;
    __syncthreads();

    int nIter = K / 16;
    for (int it = 0; it < nIter; it++){
        int buf = it & 1;
        float4 na0, nb0;
        if (it + 1 < nIter){
            int koff = (it+1)*16;
            na0 = av0 ? *(const float4*)(Ap0 + koff) : make_float4(0,0,0,0);
            nb0 = *(const float4*)(Bp0 + koff);
        }
        #pragma unroll
        for (int kk = 0; kk < 16; kk++){
            float ar[8], br[4];
            *(float4*)(ar)   = *(const float4*)&As[buf][kk][ty*8];
            *(float4*)(ar+4) = *(const float4*)&As[buf][kk][ty*8+4];
            *(float4*)(br)   = *(const float4*)&Bs[buf][kk][tx*4];
            #pragma unroll
            for (int r = 0; r < 8; r++)
                #pragma unroll
                for (int q = 0; q < 4; q++)
                    acc[r][q] = fmaf(ar[r], br[q], acc[r][q]);
        }
        if (it + 1 < nIter){
            int nb = buf ^ 1;
            __syncthreads();
            As[nb][c0+0][r0]=na0.x; As[nb][c0+1][r0]=na0.y; As[nb][c0+2][r0]=na0.z; As[nb][c0+3][r0]=na0.w;
            Bs[nb][c0+0][r0]=nb0.x; Bs[nb][c0+1][r0]=nb0.y; Bs[nb][c0+2][r0]=nb0.z; Bs[nb][c0+3][r0]=nb0.w;
            __syncthreads();
        }
    }
    #pragma unroll
    for (int r = 0; r < 8; r++){
        int row = mbase + ty*8 + r;
        if (row < M){
            #pragma unroll
            for (int q = 0; q < 4; q++){
                int col = nbase + tx*4 + q;
                Cmat[(size_t)row*N + col] = fmaxf(__fadd_rn(acc[r][q], bias[col]), 0.f);
            }
        }
    }
}

// ---------------- RCNN heads + decode2 (fp64 dots — cheap, proven path) ----------------
__global__ void __launch_bounds__(192) k_heads(const float* __restrict__ cw, const float* __restrict__ cb,
                                               const float* __restrict__ rw, const float* __restrict__ rb,
                                               float* __restrict__ out){
    __shared__ float sd[6];
    int k = blockIdx.x;
    int warp = threadIdx.x >> 5, lane = threadIdx.x & 31;
    const float4* h4 = (const float4*)(g_h2 + (size_t)k*1024);
    const float4* w4 = (const float4*)((warp < 2) ? (cw + warp*1024) : (rw + (warp-2)*1024));
    double acc = 0.0;
    #pragma unroll
    for (int q = 0; q < 8; q++){
        float4 a = h4[lane + q*32], b = w4[lane + q*32];
        acc = fma((double)a.x, (double)b.x, acc);
        acc = fma((double)a.y, (double)b.y, acc);
        acc = fma((double)a.z, (double)b.z, acc);
        acc = fma((double)a.w, (double)b.w, acc);
    }
    #pragma unroll
    for (int o = 16; o; o >>= 1) acc += __shfl_xor_sync(FULLM, acc, o);
    if (lane == 0) sd[warp] = __fadd_rn((float)acc, (warp < 2) ? cb[warp] : rb[warp-2]);
    __syncthreads();
    if (threadIdx.x == 0){
        float l0 = sd[0], l1 = sd[1];
        out[O_RCL + k*2+0] = l0; out[O_RCL + k*2+1] = l1;
        float d0 = sd[2], d1 = sd[3], d2 = sd[4], d3 = sd[5];
        out[O_RCD + k*4+0]=d0; out[O_RCD + k*4+1]=d1;
        out[O_RCD + k*4+2]=d2; out[O_RCD + k*4+3]=d3;
        float score = softmax1(l0, l1);
        float4 pr = ((const float4*)g_prop4)[k];
        float w = __fadd_rn(__fsub_rn(pr.z, pr.x), 1.f);
        float h = __fadd_rn(__fsub_rn(pr.w, pr.y), 1.f);
        float ccx = __fadd_rn(pr.x, __fmul_rn(0.5f, w));
        float ccy = __fadd_rn(pr.y, __fmul_rn(0.5f, h));
        float pcx = __fadd_rn(__fmul_rn(d0, w), ccx);
        float pcy = __fadd_rn(__fmul_rn(d1, h), ccy);
        float pw = __fmul_rn(exp_strict(d2), w);
        float ph = __fmul_rn(exp_strict(d3), h);
        float hw = __fmul_rn(0.5f, pw), hh = __fmul_rn(0.5f, ph);
        float4 dt;
        dt.x = fminf(fmaxf(__fsub_rn(pcx, hw), 0.f), 511.f);
        dt.y = fminf(fmaxf(__fsub_rn(pcy, hh), 0.f), 511.f);
        dt.z = fminf(fmaxf(__fadd_rn(pcx, hw), 0.f), 511.f);
        dt.w = fminf(fmaxf(__fadd_rn(pcy, hh), 0.f), 511.f);
        ((float4*)g_dets)[k] = dt;
        g_rsc[k] = score;
        g_key2[k] = score;
        g_idx2[k] = k;
    }
}

// ---------------- final outputs ----------------
__global__ void k_final(float* __restrict__ out){
    int i = blockIdx.x*blockDim.x + threadIdx.x;
    if (i < KP){
        float m = (i < g_nk2) ? 1.f : 0.f;
        int id = g_keep2[i];
        float4 d = ((const float4*)g_dets)[id];
        out[O_DETS + i*4+0] = d.x*m; out[O_DETS + i*4+1] = d.y*m;
        out[O_DETS + i*4+2] = d.z*m; out[O_DETS + i*4+3] = d.w*m;
        out[O_SC + i] = g_rsc[id]*m;
    }
}

// ---------------- launch ----------------
extern "C" void kernel_launch(void* const* d_in, const int* in_sizes, int n_in,
                              void* d_out, int out_size){
    const float* x        = (const float*)d_in[0];
    const float* bb_w     = (const float*)d_in[1];
    const float* bb_b     = (const float*)d_in[2];
    const float* rpn_w    = (const float*)d_in[3];
    const float* rpn_b    = (const float*)d_in[4];
    const float* rpn_cls_w= (const float*)d_in[5];
    const float* rpn_cls_b= (const float*)d_in[6];
    const float* rpn_reg_w= (const float*)d_in[7];
    const float* rpn_reg_b= (const float*)d_in[8];
    const float* fc1_w    = (const float*)d_in[9];
    const float* fc1_b    = (const float*)d_in[10];
    const float* fc2_w    = (const float*)d_in[11];
    const float* fc2_b    = (const float*)d_in[12];
    const float* cls_w    = (const float*)d_in[13];
    const float* cls_b    = (const float*)d_in[14];
    const float* reg_w    = (const float*)d_in[15];
    const float* reg_b    = (const float*)d_in[16];
    float* out = (float*)d_out;

    float *p_key1, *p_key2, *p_sbox1, *p_sdet, *p_flat, *p_fc1wP, *p_h1, *p_h2;
    int *p_idx1, *p_idx2;
    unsigned long long *p_mask1, *p_mask2;
    cudaGetSymbolAddress((void**)&p_key1,  g_key1);
    cudaGetSymbolAddress((void**)&p_idx1,  g_idx1);
    cudaGetSymbolAddress((void**)&p_key2,  g_key2);
    cudaGetSymbolAddress((void**)&p_idx2,  g_idx2);
    cudaGetSymbolAddress((void**)&p_sbox1, g_sbox1);
    cudaGetSymbolAddress((void**)&p_sdet,  g_sdet);
    cudaGetSymbolAddress((void**)&p_mask1, g_mask1);
    cudaGetSymbolAddress((void**)&p_mask2, g_mask2);
    cudaGetSymbolAddress((void**)&p_flat,  g_flat);
    cudaGetSymbolAddress((void**)&p_fc1wP, g_fc1wP);
    cudaGetSymbolAddress((void**)&p_h1,    g_h1);
    cudaGetSymbolAddress((void**)&p_h2,    g_h2);

    k_transpose<<<(768*128+255)/256, 256>>>(bb_w, 768, 0);
    k_transpose<<<(1152*128+255)/256, 256>>>(rpn_w, 1152, 1);
    k_tfc1<<<1024, 256>>>(fc1_w);
    k_init<<<32, 256>>>();

    k_conv1<<<256, 128>>>(x, bb_b);
    k_conv2<<<256, 128>>>(rpn_b);
    k_rpn<<<1024, 64>>>(rpn_cls_w, rpn_cls_b, rpn_reg_w, rpn_reg_b, out);

    // hybrid bitonic sort over 16384 (desc score, tie idx asc)
    k_sort_local<<<8, 1024>>>(p_key1, p_idx1);
    for (int kk = 4096; kk <= NPAD1; kk <<= 1){
        for (int j = kk >> 1; j >= 2048; j >>= 1)
            k_sort_global<<<NPAD1/256, 256>>>(p_key1, p_idx1, kk, j, NPAD1);
        k_merge_local<<<8, 1024>>>(p_key1, p_idx1, kk);
    }

    k_gather1<<<(NANCH+255)/256, 256>>>();
    {
        dim3 g(NBW1, NBW1);
        k_mask<<<g, 64>>>(p_sbox1, NANCH, NBW1, p_mask1, 0.5f);
    }
    k_scan1<<<1, 32>>>();
    k_props<<<(KP+255)/256, 256>>>(out);
    k_crop<<<KP, 256>>>();

    {
        dim3 g1(8, 16);
        k_gemm<<<g1, 512>>>(p_flat, p_fc1wP, fc1_b, p_h1, KP, 1024, FK);
        k_gemm<<<g1, 512>>>(p_h1, fc2_w, fc2_b, p_h2, KP, 1024, 1024);
    }
    k_heads<<<KP, 192>>>(cls_w, cls_b, reg_w, reg_b, out);

    k_sort_local<<<1, 1024>>>(p_key2, p_idx2);

    k_gather2<<<(KP+255)/256, 256>>>();
    {
        dim3 g(NBW2, NBW2);
        k_mask<<<g, 64>>>(p_sdet, KP, NBW2, p_mask2, 0.3f);
    }
    k_scan2<<<1, 32>>>();
    k_final<<<(KP+255)/256, 256>>>(out);
}